// round 9
// baseline (speedup 1.0000x reference)
#include <cuda_runtime.h>

#define NVOX   262144
#define NU     65536
#define C_IN   128
#define C_HID  64
#define K_OUT  20
#define TILE   128
#define NTILES (NVOX / TILE)
#define HSV    130           // hs row stride, [j][v]
#define THREADS 512

typedef unsigned long long u64;

__device__ __forceinline__ u64 bcast2(float a) {
    u64 r; asm("mov.b64 %0, {%1, %1};" : "=l"(r) : "f"(a)); return r;
}
__device__ __forceinline__ u64 pack2(float a, float b) {
    u64 r; asm("mov.b64 %0, {%1, %2};" : "=l"(r) : "f"(a), "f"(b)); return r;
}
__device__ __forceinline__ void fma2(u64& d, u64 a, u64 b) {
    asm("fma.rn.f32x2 %0, %1, %2, %0;" : "+l"(d) : "l"(a), "l"(b));
}
__device__ __forceinline__ u64 add2(u64 a, u64 b) {
    u64 r; asm("add.rn.f32x2 %0, %1, %2;" : "=l"(r) : "l"(a), "l"(b)); return r;
}
__device__ __forceinline__ float2 unpk(u64 v) {
    float2 r; asm("mov.b64 {%0, %1}, %2;" : "=f"(r.x), "=f"(r.y) : "l"(v)); return r;
}
__device__ __forceinline__ float leaky(float x) {
    return fmaxf(x, 0.f) + 0.01f * fminf(x, 0.f);
}

__device__ int   g_rank[NVOX];
__device__ float g_W23[C_HID * C_HID];
__device__ float g_b23[C_HID];

__global__ void rank_kernel(const int* __restrict__ ui, const int* __restrict__ mi) {
    int t = blockIdx.x * blockDim.x + threadIdx.x;
    if (t < NU)        g_rank[ui[t]]      = t;
    else if (t < NVOX) g_rank[mi[t - NU]] = -1;
}

// W23 = w2 @ sdb_w  [64j x 64j2], b23 = b2 @ sdb_w + sdb_b
__global__ void w23_kernel(const float* __restrict__ w2, const float* __restrict__ sdb_w,
                           const float* __restrict__ b2, const float* __restrict__ sdb_b) {
    int idx = blockIdx.x * blockDim.x + threadIdx.x;
    if (idx < C_HID * C_HID) {
        int j = idx >> 6, j2 = idx & 63;
        float acc = 0.f;
        #pragma unroll 8
        for (int c = 0; c < C_IN; ++c)
            acc += w2[j * C_IN + c] * sdb_w[c * C_HID + j2];
        g_W23[idx] = acc;
    }
    if (idx < C_HID) {
        float acc = sdb_b[idx];
        #pragma unroll 8
        for (int c = 0; c < C_IN; ++c)
            acc += b2[c] * sdb_w[c * C_HID + idx];
        g_b23[idx] = acc;
    }
}

struct __align__(16) Smem {
    float fs[C_IN * TILE];        // [c][v] feats, read-only after load
    float hs[C_HID * HSV];        // [j][v] raw h -> normalized h -> d
    float w1s [C_IN * C_HID];     // [c][j]
    float sdbs[C_IN * C_HID];     // [c][j2]
    float W23s[C_HID * C_HID];    // [j][j2]
    float sscs[C_HID * K_OUT];    // [j2][k]
    float auxs[C_IN * K_OUT];     // [c][k]
    float b1s[C_HID], lngs[C_HID], lnbs[C_HID], sdbbs[C_HID], b23s[C_HID];
    float sscbs[K_OUT], auxbs[K_OUT];
    float mus[TILE], rss[TILE];
    u64   red1u[8 * 64], red2u[8 * 64];
    int   ranks[TILE];
    int   lstv[TILE], lstr[TILE];
    int   cnt, pad[3];
};

__global__ void __launch_bounds__(THREADS, 1)
fused_kernel(const float* __restrict__ x3d,
             const float* __restrict__ w1,    const float* __restrict__ b1,
             const float* __restrict__ ln_g,  const float* __restrict__ ln_b,
             const float* __restrict__ sdb_w, const float* __restrict__ sdb_b,
             const float* __restrict__ ssc_w, const float* __restrict__ ssc_b,
             const float* __restrict__ aux_w, const float* __restrict__ aux_b,
             float* __restrict__ out)
{
    extern __shared__ char smem_raw[];
    Smem* s = reinterpret_cast<Smem*>(smem_raw);
    const int t = threadIdx.x;
    const int warp = t >> 5, lane = t & 31;

    for (int i = t; i < C_IN * C_HID;   i += THREADS) s->w1s[i]  = w1[i];
    for (int i = t; i < C_IN * C_HID;   i += THREADS) s->sdbs[i] = sdb_w[i];
    for (int i = t; i < C_HID * C_HID;  i += THREADS) s->W23s[i] = g_W23[i];
    for (int i = t; i < C_HID * K_OUT;  i += THREADS) s->sscs[i] = ssc_w[i];
    for (int i = t; i < C_IN * K_OUT;   i += THREADS) s->auxs[i] = aux_w[i];
    if (t < C_HID) {
        s->b1s[t] = b1[t]; s->lngs[t] = ln_g[t]; s->lnbs[t] = ln_b[t];
        s->sdbbs[t] = sdb_b[t]; s->b23s[t] = g_b23[t];
    }
    if (t < K_OUT) { s->sscbs[t] = ssc_b[t]; s->auxbs[t] = aux_b[t]; }

    float* outsem = out + (size_t)K_OUT * NVOX;

    // GEMM1: warp = 1 j-block x 32 v-pairs (w loads warp-uniform)
    const int jb1 = warp & 7, vh1 = warp >> 3;
    const int v0g = (vh1 * 32 + lane) * 2;
    const int j0g = jb1 * 8;
    // pass A: thread = v-pair (t&63) x 8 j2 (t>>6); W23 loads warp-uniform
    const int v0A = (t & 63) * 2;
    const int j2A = (t >> 6) * 8;

    for (int tile = blockIdx.x; tile < NTILES; tile += gridDim.x) {
        const int vbase = tile * TILE;
        __syncthreads();
        if (t == 0) s->cnt = 0;

        // ---- load feats tile [128 c][128 v] ----
        #pragma unroll
        for (int it = 0; it < 8; ++it) {
            int i  = t + it * THREADS;
            int c  = i >> 5;
            int vq = i & 31;
            *reinterpret_cast<float4*>(&s->fs[c * TILE + vq * 4]) =
                *reinterpret_cast<const float4*>(&x3d[(size_t)c * NVOX + vbase + vq * 4]);
        }
        if (t < TILE) s->ranks[t] = g_rank[vbase + t];
        __syncthreads();
        if (t < TILE) {
            int r = s->ranks[t];
            if (r >= 0) { int p = atomicAdd(&s->cnt, 1); s->lstv[p] = t; s->lstr[p] = r; }
        }

        // ---- GEMM1: raw h = feats @ w1 + b1 -> hs[j][v]  (software-pipelined) ----
        {
            u64 acc[2][4];    // [vv][j-pair]
            {
                const u64* bp = reinterpret_cast<const u64*>(s->b1s + j0g);
                #pragma unroll
                for (int jp = 0; jp < 4; ++jp) { acc[0][jp] = bp[jp]; acc[1][jp] = bp[jp]; }
            }
            const float* fp = s->fs + v0g;
            const float* wp = s->w1s + j0g;
            float2 fc = *reinterpret_cast<const float2*>(fp);
            ulonglong2 wac = *reinterpret_cast<const ulonglong2*>(wp);
            ulonglong2 wbc = *reinterpret_cast<const ulonglong2*>(wp + 4);
            #pragma unroll 4
            for (int c = 0; c < C_IN; ++c) {
                float2 fn; ulonglong2 wan, wbn;
                if (c + 1 < C_IN) {
                    fn  = *reinterpret_cast<const float2*>(fp + (c + 1) * TILE);
                    wan = *reinterpret_cast<const ulonglong2*>(wp + (c + 1) * C_HID);
                    wbn = *reinterpret_cast<const ulonglong2*>(wp + (c + 1) * C_HID + 4);
                }
                u64 d0 = bcast2(fc.x), d1 = bcast2(fc.y);
                fma2(acc[0][0], d0, wac.x); fma2(acc[1][0], d1, wac.x);
                fma2(acc[0][1], d0, wac.y); fma2(acc[1][1], d1, wac.y);
                fma2(acc[0][2], d0, wbc.x); fma2(acc[1][2], d1, wbc.x);
                fma2(acc[0][3], d0, wbc.y); fma2(acc[1][3], d1, wbc.y);
                fc = fn; wac = wan; wbc = wbn;
            }
            #pragma unroll
            for (int jp = 0; jp < 4; ++jp) {
                float2 q0 = unpk(acc[0][jp]);   // (j0+2jp, j0+2jp+1) @ v0g
                float2 q1 = unpk(acc[1][jp]);   // @ v0g+1
                *reinterpret_cast<u64*>(&s->hs[(j0g + 2*jp)     * HSV + v0g]) = pack2(q0.x, q1.x);
                *reinterpret_cast<u64*>(&s->hs[(j0g + 2*jp + 1) * HSV + v0g]) = pack2(q0.y, q1.y);
            }
        }
        __syncthreads();

        // ---- LayerNorm stats, f32x2 over v-pairs (8 partials per pair) ----
        {
            int vp = t & 63, q = t >> 6;
            u64 sum2 = 0, ssum2 = 0;
            #pragma unroll
            for (int jj = 0; jj < 8; ++jj) {
                u64 x2 = *reinterpret_cast<const u64*>(&s->hs[(q * 8 + jj) * HSV + vp * 2]);
                sum2 = add2(sum2, x2);
                fma2(ssum2, x2, x2);
            }
            s->red1u[q * 64 + vp] = sum2;
            s->red2u[q * 64 + vp] = ssum2;
        }
        __syncthreads();
        if (t < 64) {
            u64 s1 = 0, s2 = 0;
            #pragma unroll
            for (int q = 0; q < 8; ++q) {
                s1 = add2(s1, s->red1u[q * 64 + t]);
                s2 = add2(s2, s->red2u[q * 64 + t]);
            }
            float2 su = unpk(s1), ss = unpk(s2);
            float mu0 = su.x * (1.f / 64.f), mu1 = su.y * (1.f / 64.f);
            float var0 = ss.x * (1.f / 64.f) - mu0 * mu0;
            float var1 = ss.y * (1.f / 64.f) - mu1 * mu1;
            s->mus[2 * t]     = mu0;  s->rss[2 * t]     = rsqrtf(var0 + 1e-5f);
            s->mus[2 * t + 1] = mu1;  s->rss[2 * t + 1] = rsqrtf(var1 + 1e-5f);
        }
        __syncthreads();

        // ---- LN apply + leaky, u64 pairs ----
        #pragma unroll
        for (int it = 0; it < 8; ++it) {
            int i = t + it * THREADS;          // 0..4095 v-pairs x j
            int j = i >> 6, vp = i & 63;
            int v0 = vp * 2;
            float g = s->lngs[j], bb = s->lnbs[j];
            u64 x2 = *reinterpret_cast<const u64*>(&s->hs[j * HSV + v0]);
            float2 x = unpk(x2);
            x.x = leaky((x.x - s->mus[v0])     * s->rss[v0]     * g + bb);
            x.y = leaky((x.y - s->mus[v0 + 1]) * s->rss[v0 + 1] * g + bb);
            *reinterpret_cast<u64*>(&s->hs[j * HSV + v0]) = pack2(x.x, x.y);
        }
        __syncthreads();

        // ---- pass A: d_masked = leaky(h_norm @ W23 + b23), K=64, in-place (pipelined) ----
        {
            u64 acc[2][4];
            {
                const u64* bp = reinterpret_cast<const u64*>(s->b23s + j2A);
                #pragma unroll
                for (int jp = 0; jp < 4; ++jp) { acc[0][jp] = bp[jp]; acc[1][jp] = bp[jp]; }
            }
            const float* hp = &s->hs[v0A];
            const float* wp = s->W23s + j2A;
            float2 fc = *reinterpret_cast<const float2*>(hp);
            ulonglong2 wac = *reinterpret_cast<const ulonglong2*>(wp);
            ulonglong2 wbc = *reinterpret_cast<const ulonglong2*>(wp + 4);
            #pragma unroll 4
            for (int j = 0; j < C_HID; ++j) {
                float2 fn; ulonglong2 wan, wbn;
                if (j + 1 < C_HID) {
                    fn  = *reinterpret_cast<const float2*>(hp + (j + 1) * HSV);
                    wan = *reinterpret_cast<const ulonglong2*>(wp + (j + 1) * C_HID);
                    wbn = *reinterpret_cast<const ulonglong2*>(wp + (j + 1) * C_HID + 4);
                }
                u64 d0 = bcast2(fc.x), d1 = bcast2(fc.y);
                fma2(acc[0][0], d0, wac.x); fma2(acc[1][0], d1, wac.x);
                fma2(acc[0][1], d0, wac.y); fma2(acc[1][1], d1, wac.y);
                fma2(acc[0][2], d0, wbc.x); fma2(acc[1][2], d1, wbc.x);
                fma2(acc[0][3], d0, wbc.y); fma2(acc[1][3], d1, wbc.y);
                fc = fn; wac = wan; wbc = wbn;
            }
            __syncthreads();                   // all reads of h complete
            #pragma unroll
            for (int jp = 0; jp < 4; ++jp) {
                float2 q0 = unpk(acc[0][jp]);
                float2 q1 = unpk(acc[1][jp]);
                *reinterpret_cast<u64*>(&s->hs[(j2A + 2*jp)     * HSV + v0A]) =
                    pack2(leaky(q0.x), leaky(q1.x));
                *reinterpret_cast<u64*>(&s->hs[(j2A + 2*jp + 1) * HSV + v0A]) =
                    pack2(leaky(q0.y), leaky(q1.y));
            }
        }
        __syncthreads();

        // ---- pass B: overwrite unmasked columns: d = leaky(feats @ sdb_w + sdb_b), K=128 ----
        {
            const int nu = s->cnt;
            for (int i = t; i < nu * 16; i += THREADS) {
                int u = i >> 4, qb = i & 15;
                int v = s->lstv[u];
                const int j20 = qb * 4;
                u64 a0, a1;
                {
                    const u64* bp = reinterpret_cast<const u64*>(s->sdbbs + j20);
                    a0 = bp[0]; a1 = bp[1];
                }
                const float* fcol = &s->fs[v];
                const float* wp = s->sdbs + j20;
                #pragma unroll 4
                for (int c = 0; c < C_IN; ++c) {
                    u64 fb = bcast2(fcol[c * TILE]);
                    ulonglong2 w = *reinterpret_cast<const ulonglong2*>(wp + c * C_HID);
                    fma2(a0, fb, w.x);
                    fma2(a1, fb, w.y);
                }
                float2 q0 = unpk(a0), q1 = unpk(a1);
                s->hs[(j20)     * HSV + v] = leaky(q0.x);
                s->hs[(j20 + 1) * HSV + v] = leaky(q0.y);
                s->hs[(j20 + 2) * HSV + v] = leaky(q1.x);
                s->hs[(j20 + 3) * HSV + v] = leaky(q1.y);
            }
        }
        __syncthreads();

        // ---- heads: warps 0-9 SSC (k-pair each), warps 10-15 AUX ----
        if (warp < 10) {
            const int k0 = warp * 2;
            u64 acc[4];
            {
                u64 b = pack2(s->sscbs[k0], s->sscbs[k0 + 1]);
                #pragma unroll
                for (int q = 0; q < 4; ++q) acc[q] = b;
            }
            const float* hp = &s->hs[lane];
            const float* wp = &s->sscs[k0];
            #pragma unroll 4
            for (int j = 0; j < C_HID; ++j) {
                u64 wpair = *reinterpret_cast<const u64*>(wp + j * K_OUT);
                fma2(acc[0], bcast2(hp[j * HSV]),      wpair);
                fma2(acc[1], bcast2(hp[j * HSV + 32]), wpair);
                fma2(acc[2], bcast2(hp[j * HSV + 64]), wpair);
                fma2(acc[3], bcast2(hp[j * HSV + 96]), wpair);
            }
            float* o0 = &out[(size_t)k0 * NVOX + vbase];
            float* o1 = &out[(size_t)(k0 + 1) * NVOX + vbase];
            #pragma unroll
            for (int q = 0; q < 4; ++q) {
                float2 pr = unpk(acc[q]);
                o0[lane + 32 * q] = pr.x;
                o1[lane + 32 * q] = pr.y;
            }
        } else {
            const int nu = s->cnt;
            for (int i = lane + (warp - 10) * 32; i < nu; i += 192) {
                int v = s->lstv[i], r = s->lstr[i];
                u64 acc[10];
                const u64* bb = reinterpret_cast<const u64*>(s->auxbs);
                #pragma unroll
                for (int kp = 0; kp < 10; ++kp) acc[kp] = bb[kp];
                const float* fcol = &s->fs[v];
                #pragma unroll 4
                for (int c = 0; c < C_IN; ++c) {
                    u64 fb = bcast2(fcol[c * TILE]);
                    const u64* wr = reinterpret_cast<const u64*>(&s->auxs[c * K_OUT]);
                    #pragma unroll
                    for (int kp = 0; kp < 10; ++kp) fma2(acc[kp], fb, wr[kp]);
                }
                u64* orow = reinterpret_cast<u64*>(&outsem[(size_t)r * K_OUT]);
                #pragma unroll
                for (int kp = 0; kp < 10; ++kp) orow[kp] = acc[kp];
            }
        }
    }
}

extern "C" void kernel_launch(void* const* d_in, const int* in_sizes, int n_in,
                              void* d_out, int out_size)
{
    const float* x3d   = (const float*)d_in[0];
    const float* w1    = (const float*)d_in[1];
    const float* b1    = (const float*)d_in[2];
    const float* ln_g  = (const float*)d_in[3];
    const float* ln_b  = (const float*)d_in[4];
    const float* w2    = (const float*)d_in[5];
    const float* b2    = (const float*)d_in[6];
    const float* sdb_w = (const float*)d_in[7];
    const float* sdb_b = (const float*)d_in[8];
    const float* ssc_w = (const float*)d_in[9];
    const float* ssc_b = (const float*)d_in[10];
    const float* aux_w = (const float*)d_in[11];
    const float* aux_b = (const float*)d_in[12];
    const int* ui      = (const int*)d_in[13];
    const int* mi      = (const int*)d_in[14];
    float* out         = (float*)d_out;

    int nsm = 0;
    cudaDeviceGetAttribute(&nsm, cudaDevAttrMultiProcessorCount, 0);
    if (nsm <= 0) nsm = 148;

    cudaFuncSetAttribute(fused_kernel,
                         cudaFuncAttributeMaxDynamicSharedMemorySize,
                         (int)sizeof(Smem));

    rank_kernel<<<NVOX / 256, 256>>>(ui, mi);
    w23_kernel<<<16, 256>>>(w2, sdb_w, b2, sdb_b);
    fused_kernel<<<nsm, THREADS, sizeof(Smem)>>>(x3d, w1, b1, ln_g, ln_b,
                                                 sdb_w, sdb_b, ssc_w, ssc_b,
                                                 aux_w, aux_b, out);
}

// round 11
// speedup vs baseline: 1.7113x; 1.7113x over previous
#include <cuda_runtime.h>
#include <cuda_bf16.h>

#define NVOX   262144
#define NU     65536
#define C_IN   128
#define C_HID  64
#define K_OUT  20
#define TILE   128
#define NTILES (NVOX / TILE)
#define SA     136        // feats/B1/B3/B4 row stride (bf16 elems)
#define SH     72         // H,d / B2,B5 row stride
#define THREADS 512

typedef unsigned int u32;
typedef unsigned short u16;

__device__ __forceinline__ float leaky(float x) {
    return fmaxf(x, 0.f) + 0.01f * fminf(x, 0.f);
}
__device__ __forceinline__ u16 f2bf(float x) {
    return __bfloat16_as_ushort(__float2bfloat16(x));
}
__device__ __forceinline__ float bf2f(u16 b) {
    return __bfloat162float(__ushort_as_bfloat16(b));
}
// split two floats into packed bf16 hi / lo residual words
__device__ __forceinline__ void split2(float x0, float x1, u32& hi, u32& lo) {
    u16 h0 = f2bf(x0), h1 = f2bf(x1);
    u16 l0 = f2bf(x0 - bf2f(h0)), l1 = f2bf(x1 - bf2f(h1));
    hi = (u32)h0 | ((u32)h1 << 16);
    lo = (u32)l0 | ((u32)l1 << 16);
}
__device__ __forceinline__ u32 smem_u32(const void* p) {
    u32 a; asm("{ .reg .u64 t; cvta.to.shared.u64 t, %1; cvt.u32.u64 %0, t; }" : "=r"(a) : "l"(p));
    return a;
}
__device__ __forceinline__ void ldsm4(u32* r, u32 addr) {
    asm volatile("ldmatrix.sync.aligned.m8n8.x4.shared.b16 {%0,%1,%2,%3}, [%4];"
                 : "=r"(r[0]), "=r"(r[1]), "=r"(r[2]), "=r"(r[3]) : "r"(addr));
}
__device__ __forceinline__ void ldsm2(u32* r, u32 addr) {
    asm volatile("ldmatrix.sync.aligned.m8n8.x2.shared.b16 {%0,%1}, [%2];"
                 : "=r"(r[0]), "=r"(r[1]) : "r"(addr));
}
__device__ __forceinline__ void mmab(float* c, const u32* a, u32 b0, u32 b1) {
    asm volatile("mma.sync.aligned.m16n8k16.row.col.f32.bf16.bf16.f32 "
                 "{%0,%1,%2,%3}, {%4,%5,%6,%7}, {%8,%9}, {%0,%1,%2,%3};"
                 : "+f"(c[0]), "+f"(c[1]), "+f"(c[2]), "+f"(c[3])
                 : "r"(a[0]), "r"(a[1]), "r"(a[2]), "r"(a[3]), "r"(b0), "r"(b1));
}

__device__ int   g_rank[NVOX];
__device__ float g_W23[C_HID * C_HID];
__device__ float g_b23[C_HID];

__global__ void rank_kernel(const int* __restrict__ ui, const int* __restrict__ mi) {
    int t = blockIdx.x * blockDim.x + threadIdx.x;
    if (t < NU)        g_rank[ui[t]]      = t;
    else if (t < NVOX) g_rank[mi[t - NU]] = -1;
}

__global__ void w23_kernel(const float* __restrict__ w2, const float* __restrict__ sdb_w,
                           const float* __restrict__ b2, const float* __restrict__ sdb_b) {
    int idx = blockIdx.x * blockDim.x + threadIdx.x;
    if (idx < C_HID * C_HID) {
        int j = idx >> 6, j2 = idx & 63;
        float acc = 0.f;
        #pragma unroll 8
        for (int c = 0; c < C_IN; ++c) acc += w2[j * C_IN + c] * sdb_w[c * C_HID + j2];
        g_W23[idx] = acc;
    }
    if (idx < C_HID) {
        float acc = sdb_b[idx];
        #pragma unroll 8
        for (int c = 0; c < C_IN; ++c) acc += b2[c] * sdb_w[c * C_HID + idx];
        g_b23[idx] = acc;
    }
}

struct Smem {
    u16 Ah[128 * SA], Al[128 * SA];     // feats; later H / d at stride SH
    u16 B1h[64 * SA], B1l[64 * SA];     // w1   [j][c]
    u16 B3h[64 * SA], B3l[64 * SA];     // sdb  [j][c]
    u16 B4h[24 * SA], B4l[24 * SA];     // aux  [k][c] rows 20-23 zero
    u16 B2h[64 * SH], B2l[64 * SH];     // W23  [j2][j]
    u16 B5h[24 * SH], B5l[24 * SH];     // ssc  [k][j2] rows 20-23 zero
    float b1s[64], lngs[64], lnbs[64], sdbbs[64], b23s[64];
    float sscbs[24], auxbs[24];
    float mus[128], rss[128];
    float red1[256], red2[256];
    int   ranks[128];
};

__global__ void __launch_bounds__(THREADS, 1)
fused_kernel(const float* __restrict__ x3d,
             const float* __restrict__ w1,    const float* __restrict__ b1,
             const float* __restrict__ ln_g,  const float* __restrict__ ln_b,
             const float* __restrict__ sdb_w, const float* __restrict__ sdb_b,
             const float* __restrict__ ssc_w, const float* __restrict__ ssc_b,
             const float* __restrict__ aux_w, const float* __restrict__ aux_b,
             float* __restrict__ out)
{
    extern __shared__ char smem_raw[];
    Smem* s = reinterpret_cast<Smem*>(smem_raw);
    const int t = threadIdx.x;
    const int warp = t >> 5, lane = t & 31;

    // ---- one-time init ----
    for (int i = t; i < 24 * SA; i += THREADS) { s->B4h[i] = 0; s->B4l[i] = 0; }
    for (int i = t; i < 24 * SH; i += THREADS) { s->B5h[i] = 0; s->B5l[i] = 0; }
    __syncthreads();
    for (int i = t; i < 64 * 128; i += THREADS) {
        int j = i & 63, c = i >> 6;
        float x = w1[c * C_HID + j];
        u16 h = f2bf(x); s->B1h[j * SA + c] = h; s->B1l[j * SA + c] = f2bf(x - bf2f(h));
        x = sdb_w[c * C_HID + j];
        h = f2bf(x); s->B3h[j * SA + c] = h; s->B3l[j * SA + c] = f2bf(x - bf2f(h));
    }
    for (int i = t; i < K_OUT * 128; i += THREADS) {
        int k = i % K_OUT, c = i / K_OUT;
        float x = aux_w[c * K_OUT + k];
        u16 h = f2bf(x); s->B4h[k * SA + c] = h; s->B4l[k * SA + c] = f2bf(x - bf2f(h));
    }
    for (int i = t; i < 64 * 64; i += THREADS) {
        int j2 = i & 63, j = i >> 6;
        float x = g_W23[j * C_HID + j2];
        u16 h = f2bf(x); s->B2h[j2 * SH + j] = h; s->B2l[j2 * SH + j] = f2bf(x - bf2f(h));
    }
    for (int i = t; i < 64 * K_OUT; i += THREADS) {
        int k = i % K_OUT, j = i / K_OUT;
        float x = ssc_w[j * K_OUT + k];
        u16 h = f2bf(x); s->B5h[k * SH + j] = h; s->B5l[k * SH + j] = f2bf(x - bf2f(h));
    }
    if (t < C_HID) {
        s->b1s[t] = b1[t]; s->lngs[t] = ln_g[t]; s->lnbs[t] = ln_b[t];
        s->sdbbs[t] = sdb_b[t]; s->b23s[t] = g_b23[t];
    }
    if (t < 24) { s->sscbs[t] = (t < K_OUT) ? ssc_b[t] : 0.f;
                  s->auxbs[t] = (t < K_OUT) ? aux_b[t] : 0.f; }

    float* outsem = out + (size_t)K_OUT * NVOX;

    const u32 sAh = smem_u32(s->Ah), sAl = smem_u32(s->Al);
    const u32 sB1h = smem_u32(s->B1h), sB1l = smem_u32(s->B1l);
    const u32 sB3h = smem_u32(s->B3h), sB3l = smem_u32(s->B3l);
    const u32 sB4h = smem_u32(s->B4h), sB4l = smem_u32(s->B4l);
    const u32 sB2h = smem_u32(s->B2h), sB2l = smem_u32(s->B2l);
    const u32 sB5h = smem_u32(s->B5h), sB5l = smem_u32(s->B5l);

    const int vt = warp >> 1, nh = warp & 1;
    const int v0 = vt * 16, n0 = nh * 32;
    const int qd = lane >> 3, rw = lane & 7;
    // A-fragment ldsm offset (row-major, stride SA)
    const u32 aoffA = (u32)(((v0 + rw + (qd & 1) * 8) * SA + (qd >> 1) * 8) * 2);
    // B x4 offsets: base row nb, 2 n-tiles
    #define BOFF(nb, S) ((u32)((((nb) + rw + (qd >> 1) * 8) * (S) + (qd & 1) * 8) * 2))
    const u32 b1h0 = sB1h + BOFF(n0, SA),      b1h1 = sB1h + BOFF(n0 + 16, SA);
    const u32 b1l0 = sB1l + BOFF(n0, SA),      b1l1 = sB1l + BOFF(n0 + 16, SA);
    const u32 b3h0 = sB3h + BOFF(n0, SA),      b3h1 = sB3h + BOFF(n0 + 16, SA);
    const u32 b3l0 = sB3l + BOFF(n0, SA),      b3l1 = sB3l + BOFF(n0 + 16, SA);
    const u32 ox2  = (u32)(((16 + rw) * SA + (qd & 1) * 8) * 2);          // x2 rows 16-23
    const u32 b4h  = nh ? (sB4h + ox2) : (sB4h + BOFF(0, SA));
    const u32 b4l  = nh ? (sB4l + ox2) : (sB4l + BOFF(0, SA));
    // H-side (stride SH)
    const u32 aoffH = (u32)(((v0 + rw + (qd & 1) * 8) * SH + (qd >> 1) * 8) * 2);
    const u32 b2h0 = sB2h + BOFF(n0, SH),      b2h1 = sB2h + BOFF(n0 + 16, SH);
    const u32 b2l0 = sB2l + BOFF(n0, SH),      b2l1 = sB2l + BOFF(n0 + 16, SH);
    const u32 ox2H = (u32)(((16 + rw) * SH + (qd & 1) * 8) * 2);
    const u32 b5h  = nh ? (sB5h + ox2H) : (sB5h + BOFF(0, SH));
    const u32 b5l  = nh ? (sB5l + ox2H) : (sB5l + BOFF(0, SH));

    const int rlo = v0 + (lane >> 2), rhi = rlo + 8;
    const int q4 = lane & 3;

    // feats loader mapping
    const int lv = warp * 8 + (lane & 7);
    const int lcq = (lane >> 3) * 2;

    for (int tile = blockIdx.x; tile < NTILES; tile += gridDim.x) {
        const int vbase = tile * TILE;
        __syncthreads();                    // prior tile fully consumed

        // ---- load + split feats -> Ah/Al [v][c] stride SA ----
        {
            const int gv = vbase + lv;
            #pragma unroll 4
            for (int i = 0; i < 16; ++i) {
                int c = i * 8 + lcq;
                float f0 = x3d[(size_t)c * NVOX + gv];
                float f1 = x3d[(size_t)(c + 1) * NVOX + gv];
                u32 hi, lo; split2(f0, f1, hi, lo);
                *(u32*)((char*)s->Ah + (lv * SA + c) * 2) = hi;
                *(u32*)((char*)s->Al + (lv * SA + c) * 2) = lo;
            }
        }
        if (t < TILE) s->ranks[t] = g_rank[vbase + t];
        __syncthreads();

        // ================= D1/D3/D4 (K=128, 8 k-tiles) =================
        float d1[4][4] = {}, d3[4][4] = {}, d4[2][4] = {};
        {
            const u32 aAh = sAh + aoffA, aAl = sAl + aoffA;
            #pragma unroll
            for (int kt = 0; kt < 8; ++kt) {
                const u32 ka = kt * 32;
                u32 ah[4], al[4], bh[4], bl[4];
                ldsm4(ah, aAh + ka); ldsm4(al, aAl + ka);
                // D1
                ldsm4(bh, b1h0 + ka); ldsm4(bl, b1l0 + ka);
                mmab(d1[0], ah, bh[0], bh[1]); mmab(d1[1], ah, bh[2], bh[3]);
                mmab(d1[0], ah, bl[0], bl[1]); mmab(d1[1], ah, bl[2], bl[3]);
                mmab(d1[0], al, bh[0], bh[1]); mmab(d1[1], al, bh[2], bh[3]);
                ldsm4(bh, b1h1 + ka); ldsm4(bl, b1l1 + ka);
                mmab(d1[2], ah, bh[0], bh[1]); mmab(d1[3], ah, bh[2], bh[3]);
                mmab(d1[2], ah, bl[0], bl[1]); mmab(d1[3], ah, bl[2], bl[3]);
                mmab(d1[2], al, bh[0], bh[1]); mmab(d1[3], al, bh[2], bh[3]);
                // D3
                ldsm4(bh, b3h0 + ka); ldsm4(bl, b3l0 + ka);
                mmab(d3[0], ah, bh[0], bh[1]); mmab(d3[1], ah, bh[2], bh[3]);
                mmab(d3[0], ah, bl[0], bl[1]); mmab(d3[1], ah, bl[2], bl[3]);
                mmab(d3[0], al, bh[0], bh[1]); mmab(d3[1], al, bh[2], bh[3]);
                ldsm4(bh, b3h1 + ka); ldsm4(bl, b3l1 + ka);
                mmab(d3[2], ah, bh[0], bh[1]); mmab(d3[3], ah, bh[2], bh[3]);
                mmab(d3[2], ah, bl[0], bl[1]); mmab(d3[3], ah, bl[2], bl[3]);
                mmab(d3[2], al, bh[0], bh[1]); mmab(d3[3], al, bh[2], bh[3]);
                // D4
                if (nh == 0) {
                    ldsm4(bh, b4h + ka); ldsm4(bl, b4l + ka);
                    mmab(d4[0], ah, bh[0], bh[1]); mmab(d4[1], ah, bh[2], bh[3]);
                    mmab(d4[0], ah, bl[0], bl[1]); mmab(d4[1], ah, bl[2], bl[3]);
                    mmab(d4[0], al, bh[0], bh[1]); mmab(d4[1], al, bh[2], bh[3]);
                } else {
                    ldsm2(bh, b4h + ka); ldsm2(bl, b4l + ka);
                    mmab(d4[0], ah, bh[0], bh[1]);
                    mmab(d4[0], ah, bl[0], bl[1]);
                    mmab(d4[0], al, bh[0], bh[1]);
                }
            }
        }

        // ---- AUX writeback ----
        {
            int r0v = s->ranks[rlo], r1v = s->ranks[rhi];
            if (nh == 0) {
                #pragma unroll
                for (int nt = 0; nt < 2; ++nt) {
                    int k = nt * 8 + q4 * 2;
                    if (r0v >= 0)
                        *(float2*)&outsem[(size_t)r0v * K_OUT + k] =
                            make_float2(d4[nt][0] + s->auxbs[k], d4[nt][1] + s->auxbs[k + 1]);
                    if (r1v >= 0)
                        *(float2*)&outsem[(size_t)r1v * K_OUT + k] =
                            make_float2(d4[nt][2] + s->auxbs[k], d4[nt][3] + s->auxbs[k + 1]);
                }
            } else {
                int k = 16 + q4 * 2;
                if (k < K_OUT) {
                    if (r0v >= 0)
                        *(float2*)&outsem[(size_t)r0v * K_OUT + k] =
                            make_float2(d4[0][0] + s->auxbs[k], d4[0][1] + s->auxbs[k + 1]);
                    if (r1v >= 0)
                        *(float2*)&outsem[(size_t)r1v * K_OUT + k] =
                            make_float2(d4[0][2] + s->auxbs[k], d4[0][3] + s->auxbs[k + 1]);
                }
            }
        }

        // ---- h = D1 + b1 ; LN partials (in fragment layout) ----
        {
            float slo = 0.f, qlo = 0.f, shi = 0.f, qhi = 0.f;
            #pragma unroll
            for (int nt = 0; nt < 4; ++nt) {
                int j = n0 + nt * 8 + q4 * 2;
                float bb0 = s->b1s[j], bb1 = s->b1s[j + 1];
                d1[nt][0] += bb0; d1[nt][1] += bb1; d1[nt][2] += bb0; d1[nt][3] += bb1;
                slo += d1[nt][0] + d1[nt][1];
                qlo += d1[nt][0] * d1[nt][0] + d1[nt][1] * d1[nt][1];
                shi += d1[nt][2] + d1[nt][3];
                qhi += d1[nt][2] * d1[nt][2] + d1[nt][3] * d1[nt][3];
            }
            #pragma unroll
            for (int o = 1; o < 4; o <<= 1) {
                slo += __shfl_xor_sync(0xFFFFFFFFu, slo, o);
                qlo += __shfl_xor_sync(0xFFFFFFFFu, qlo, o);
                shi += __shfl_xor_sync(0xFFFFFFFFu, shi, o);
                qhi += __shfl_xor_sync(0xFFFFFFFFu, qhi, o);
            }
            if (q4 == 0) {
                s->red1[nh * 128 + rlo] = slo; s->red2[nh * 128 + rlo] = qlo;
                s->red1[nh * 128 + rhi] = shi; s->red2[nh * 128 + rhi] = qhi;
            }
        }
        __syncthreads();
        if (t < TILE) {
            float su = s->red1[t] + s->red1[128 + t];
            float sq = s->red2[t] + s->red2[128 + t];
            float mu = su * (1.f / 64.f);
            float var = sq * (1.f / 64.f) - mu * mu;
            s->mus[t] = mu; s->rss[t] = rsqrtf(var + 1e-5f);
        }
        __syncthreads();

        // ---- normalize + leaky -> H bf16 hi/lo (overwrites A buffer, stride SH) ----
        {
            float mu0 = s->mus[rlo], rs0 = s->rss[rlo];
            float mu1 = s->mus[rhi], rs1 = s->rss[rhi];
            #pragma unroll
            for (int nt = 0; nt < 4; ++nt) {
                int j = n0 + nt * 8 + q4 * 2;
                float g0 = s->lngs[j], g1 = s->lngs[j + 1];
                float c0 = s->lnbs[j], c1 = s->lnbs[j + 1];
                float x0 = leaky((d1[nt][0] - mu0) * rs0 * g0 + c0);
                float x1 = leaky((d1[nt][1] - mu0) * rs0 * g1 + c1);
                float x2 = leaky((d1[nt][2] - mu1) * rs1 * g0 + c0);
                float x3 = leaky((d1[nt][3] - mu1) * rs1 * g1 + c1);
                u32 hi, lo;
                split2(x0, x1, hi, lo);
                *(u32*)((char*)s->Ah + (rlo * SH + j) * 2) = hi;
                *(u32*)((char*)s->Al + (rlo * SH + j) * 2) = lo;
                split2(x2, x3, hi, lo);
                *(u32*)((char*)s->Ah + (rhi * SH + j) * 2) = hi;
                *(u32*)((char*)s->Al + (rhi * SH + j) * 2) = lo;
            }
        }
        __syncthreads();

        // ================= D2 = H @ W23 (K=64, 4 k-tiles) =================
        float d2[4][4] = {};
        {
            const u32 aHh = sAh + aoffH, aHl = sAl + aoffH;
            #pragma unroll
            for (int kt = 0; kt < 4; ++kt) {
                const u32 ka = kt * 32;
                u32 ah[4], al[4], bh[4], bl[4];
                ldsm4(ah, aHh + ka); ldsm4(al, aHl + ka);
                ldsm4(bh, b2h0 + ka); ldsm4(bl, b2l0 + ka);
                mmab(d2[0], ah, bh[0], bh[1]); mmab(d2[1], ah, bh[2], bh[3]);
                mmab(d2[0], ah, bl[0], bl[1]); mmab(d2[1], ah, bl[2], bl[3]);
                mmab(d2[0], al, bh[0], bh[1]); mmab(d2[1], al, bh[2], bh[3]);
                ldsm4(bh, b2h1 + ka); ldsm4(bl, b2l1 + ka);
                mmab(d2[2], ah, bh[0], bh[1]); mmab(d2[3], ah, bh[2], bh[3]);
                mmab(d2[2], ah, bl[0], bl[1]); mmab(d2[3], ah, bl[2], bl[3]);
                mmab(d2[2], al, bh[0], bh[1]); mmab(d2[3], al, bh[2], bh[3]);
            }
        }
        __syncthreads();                    // all H reads done

        // ---- d = masked ? leaky(D2+b23) : leaky(D3+sdbb) -> bf16 hi/lo in place ----
        {
            bool m0 = s->ranks[rlo] < 0, m1 = s->ranks[rhi] < 0;
            #pragma unroll
            for (int nt = 0; nt < 4; ++nt) {
                int j = n0 + nt * 8 + q4 * 2;
                float bm0 = s->b23s[j], bm1 = s->b23s[j + 1];
                float bu0 = s->sdbbs[j], bu1 = s->sdbbs[j + 1];
                float x0 = m0 ? leaky(d2[nt][0] + bm0) : leaky(d3[nt][0] + bu0);
                float x1 = m0 ? leaky(d2[nt][1] + bm1) : leaky(d3[nt][1] + bu1);
                float x2 = m1 ? leaky(d2[nt][2] + bm0) : leaky(d3[nt][2] + bu0);
                float x3 = m1 ? leaky(d2[nt][3] + bm1) : leaky(d3[nt][3] + bu1);
                u32 hi, lo;
                split2(x0, x1, hi, lo);
                *(u32*)((char*)s->Ah + (rlo * SH + j) * 2) = hi;
                *(u32*)((char*)s->Al + (rlo * SH + j) * 2) = lo;
                split2(x2, x3, hi, lo);
                *(u32*)((char*)s->Ah + (rhi * SH + j) * 2) = hi;
                *(u32*)((char*)s->Al + (rhi * SH + j) * 2) = lo;
            }
        }
        __syncthreads();

        // ================= D5 = d @ ssc_w (K=64) =================
        float d5[2][4] = {};
        {
            const u32 aHh = sAh + aoffH, aHl = sAl + aoffH;
            #pragma unroll
            for (int kt = 0; kt < 4; ++kt) {
                const u32 ka = kt * 32;
                u32 ah[4], al[4], bh[4], bl[4];
                ldsm4(ah, aHh + ka); ldsm4(al, aHl + ka);
                if (nh == 0) {
                    ldsm4(bh, b5h + ka); ldsm4(bl, b5l + ka);
                    mmab(d5[0], ah, bh[0], bh[1]); mmab(d5[1], ah, bh[2], bh[3]);
                    mmab(d5[0], ah, bl[0], bl[1]); mmab(d5[1], ah, bl[2], bl[3]);
                    mmab(d5[0], al, bh[0], bh[1]); mmab(d5[1], al, bh[2], bh[3]);
                } else {
                    ldsm2(bh, b5h + ka); ldsm2(bl, b5l + ka);
                    mmab(d5[0], ah, bh[0], bh[1]);
                    mmab(d5[0], ah, bl[0], bl[1]);
                    mmab(d5[0], al, bh[0], bh[1]);
                }
            }
        }
        // ---- SSC writeback ----
        if (nh == 0) {
            #pragma unroll
            for (int nt = 0; nt < 2; ++nt) {
                int k = nt * 8 + q4 * 2;
                out[(size_t)k       * NVOX + vbase + rlo] = d5[nt][0] + s->sscbs[k];
                out[(size_t)(k + 1) * NVOX + vbase + rlo] = d5[nt][1] + s->sscbs[k + 1];
                out[(size_t)k       * NVOX + vbase + rhi] = d5[nt][2] + s->sscbs[k];
                out[(size_t)(k + 1) * NVOX + vbase + rhi] = d5[nt][3] + s->sscbs[k + 1];
            }
        } else {
            int k = 16 + q4 * 2;
            if (k < K_OUT) {
                out[(size_t)k       * NVOX + vbase + rlo] = d5[0][0] + s->sscbs[k];
                out[(size_t)(k + 1) * NVOX + vbase + rlo] = d5[0][1] + s->sscbs[k + 1];
                out[(size_t)k       * NVOX + vbase + rhi] = d5[0][2] + s->sscbs[k];
                out[(size_t)(k + 1) * NVOX + vbase + rhi] = d5[0][3] + s->sscbs[k + 1];
            }
        }
    }
}

extern "C" void kernel_launch(void* const* d_in, const int* in_sizes, int n_in,
                              void* d_out, int out_size)
{
    const float* x3d   = (const float*)d_in[0];
    const float* w1    = (const float*)d_in[1];
    const float* b1    = (const float*)d_in[2];
    const float* ln_g  = (const float*)d_in[3];
    const float* ln_b  = (const float*)d_in[4];
    const float* w2    = (const float*)d_in[5];
    const float* b2    = (const float*)d_in[6];
    const float* sdb_w = (const float*)d_in[7];
    const float* sdb_b = (const float*)d_in[8];
    const float* ssc_w = (const float*)d_in[9];
    const float* ssc_b = (const float*)d_in[10];
    const float* aux_w = (const float*)d_in[11];
    const float* aux_b = (const float*)d_in[12];
    const int* ui      = (const int*)d_in[13];
    const int* mi      = (const int*)d_in[14];
    float* out         = (float*)d_out;

    int nsm = 0;
    cudaDeviceGetAttribute(&nsm, cudaDevAttrMultiProcessorCount, 0);
    if (nsm <= 0) nsm = 148;

    cudaFuncSetAttribute(fused_kernel,
                         cudaFuncAttributeMaxDynamicSharedMemorySize,
                         (int)sizeof(Smem));

    rank_kernel<<<NVOX / 256, 256>>>(ui, mi);
    w23_kernel<<<16, 256>>>(w2, sdb_w, b2, sdb_b);
    fused_kernel<<<nsm, THREADS, sizeof(Smem)>>>(x3d, w1, b1, ln_g, ln_b,
                                                 sdb_w, sdb_b, ssc_w, ssc_b,
                                                 aux_w, aux_b, out);
}

// round 12
// speedup vs baseline: 1.9993x; 1.1683x over previous
#include <cuda_runtime.h>
#include <cuda_bf16.h>

#define NVOX   262144
#define NU     65536
#define NM     (NVOX - NU)
#define C_IN   128
#define C_HID  64
#define K_OUT  20
#define TILE   128
#define NMT    (NM / TILE)        // 1536 masked tiles
#define NUT    (NU / TILE)        // 512 unmasked tiles
#define NTILES (NMT + NUT)
#define SA     136                // feats/B1/B3/B4 row stride (bf16 elems)
#define SH     72                 // H,d / B2,B5 row stride
#define THREADS 512

typedef unsigned int u32;
typedef unsigned short u16;

__device__ __forceinline__ float leaky(float x) {
    return fmaxf(x, 0.f) + 0.01f * fminf(x, 0.f);
}
__device__ __forceinline__ u16 f2bf(float x) {
    return __bfloat16_as_ushort(__float2bfloat16(x));
}
__device__ __forceinline__ float bf2f(u16 b) {
    return __bfloat162float(__ushort_as_bfloat16(b));
}
__device__ __forceinline__ void split2(float x0, float x1, u32& hi, u32& lo) {
    u16 h0 = f2bf(x0), h1 = f2bf(x1);
    u16 l0 = f2bf(x0 - bf2f(h0)), l1 = f2bf(x1 - bf2f(h1));
    hi = (u32)h0 | ((u32)h1 << 16);
    lo = (u32)l0 | ((u32)l1 << 16);
}
__device__ __forceinline__ u32 smem_u32(const void* p) {
    u32 a; asm("{ .reg .u64 t; cvta.to.shared.u64 t, %1; cvt.u32.u64 %0, t; }" : "=r"(a) : "l"(p));
    return a;
}
__device__ __forceinline__ void ldsm4(u32* r, u32 addr) {
    asm volatile("ldmatrix.sync.aligned.m8n8.x4.shared.b16 {%0,%1,%2,%3}, [%4];"
                 : "=r"(r[0]), "=r"(r[1]), "=r"(r[2]), "=r"(r[3]) : "r"(addr));
}
__device__ __forceinline__ void ldsm2(u32* r, u32 addr) {
    asm volatile("ldmatrix.sync.aligned.m8n8.x2.shared.b16 {%0,%1}, [%2];"
                 : "=r"(r[0]), "=r"(r[1]) : "r"(addr));
}
__device__ __forceinline__ void mmab(float* c, const u32* a, u32 b0, u32 b1) {
    asm volatile("mma.sync.aligned.m16n8k16.row.col.f32.bf16.bf16.f32 "
                 "{%0,%1,%2,%3}, {%4,%5,%6,%7}, {%8,%9}, {%0,%1,%2,%3};"
                 : "+f"(c[0]), "+f"(c[1]), "+f"(c[2]), "+f"(c[3])
                 : "r"(a[0]), "r"(a[1]), "r"(a[2]), "r"(a[3]), "r"(b0), "r"(b1));
}

__device__ float g_W23[C_HID * C_HID];
__device__ float g_b23[C_HID];

__global__ void w23_kernel(const float* __restrict__ w2, const float* __restrict__ sdb_w,
                           const float* __restrict__ b2, const float* __restrict__ sdb_b) {
    int idx = blockIdx.x * blockDim.x + threadIdx.x;
    if (idx < C_HID * C_HID) {
        int j = idx >> 6, j2 = idx & 63;
        float acc = 0.f;
        #pragma unroll 8
        for (int c = 0; c < C_IN; ++c) acc += w2[j * C_IN + c] * sdb_w[c * C_HID + j2];
        g_W23[idx] = acc;
    }
    if (idx < C_HID) {
        float acc = sdb_b[idx];
        #pragma unroll 8
        for (int c = 0; c < C_IN; ++c) acc += b2[c] * sdb_w[c * C_HID + idx];
        g_b23[idx] = acc;
    }
}

struct Smem {
    u16 Ah[128 * SA], Al[128 * SA];     // feats (stride SA); later H / d (stride SH)
    u16 B1h[64 * SA], B1l[64 * SA];     // w1   [j][c]
    u16 B3h[64 * SA], B3l[64 * SA];     // sdb  [j][c]
    u16 B4h[24 * SA], B4l[24 * SA];     // aux  [k][c] rows 20-23 zero
    u16 B2h[64 * SH], B2l[64 * SH];     // W23  [j2][j]
    u16 B5h[24 * SH], B5l[24 * SH];     // ssc  [k][j2] rows 20-23 zero
    float b1s[64], lngs[64], lnbs[64], sdbbs[64], b23s[64];
    float sscbs[24], auxbs[24];
    float mus[128], rss[128];
    float red1[256], red2[256];
    int   vidx[128];
};

__global__ void __launch_bounds__(THREADS, 1)
fused_kernel(const float* __restrict__ x3d,
             const float* __restrict__ w1,    const float* __restrict__ b1,
             const float* __restrict__ ln_g,  const float* __restrict__ ln_b,
             const float* __restrict__ sdb_w, const float* __restrict__ sdb_b,
             const float* __restrict__ ssc_w, const float* __restrict__ ssc_b,
             const float* __restrict__ aux_w, const float* __restrict__ aux_b,
             const int* __restrict__ ui,      const int* __restrict__ mi,
             float* __restrict__ out)
{
    extern __shared__ char smem_raw[];
    Smem* s = reinterpret_cast<Smem*>(smem_raw);
    const int t = threadIdx.x;
    const int warp = t >> 5, lane = t & 31;

    // ---- one-time init: weights -> bf16 hi/lo ----
    for (int i = t; i < 24 * SA; i += THREADS) { s->B4h[i] = 0; s->B4l[i] = 0; }
    for (int i = t; i < 24 * SH; i += THREADS) { s->B5h[i] = 0; s->B5l[i] = 0; }
    __syncthreads();
    for (int i = t; i < 64 * 128; i += THREADS) {
        int j = i & 63, c = i >> 6;
        float x = w1[c * C_HID + j];
        u16 h = f2bf(x); s->B1h[j * SA + c] = h; s->B1l[j * SA + c] = f2bf(x - bf2f(h));
        x = sdb_w[c * C_HID + j];
        h = f2bf(x); s->B3h[j * SA + c] = h; s->B3l[j * SA + c] = f2bf(x - bf2f(h));
    }
    for (int i = t; i < K_OUT * 128; i += THREADS) {
        int k = i % K_OUT, c = i / K_OUT;
        float x = aux_w[c * K_OUT + k];
        u16 h = f2bf(x); s->B4h[k * SA + c] = h; s->B4l[k * SA + c] = f2bf(x - bf2f(h));
    }
    for (int i = t; i < 64 * 64; i += THREADS) {
        int j2 = i & 63, j = i >> 6;
        float x = g_W23[j * C_HID + j2];
        u16 h = f2bf(x); s->B2h[j2 * SH + j] = h; s->B2l[j2 * SH + j] = f2bf(x - bf2f(h));
    }
    for (int i = t; i < 64 * K_OUT; i += THREADS) {
        int k = i % K_OUT, j = i / K_OUT;
        float x = ssc_w[j * K_OUT + k];
        u16 h = f2bf(x); s->B5h[k * SH + j] = h; s->B5l[k * SH + j] = f2bf(x - bf2f(h));
    }
    if (t < C_HID) {
        s->b1s[t] = b1[t]; s->lngs[t] = ln_g[t]; s->lnbs[t] = ln_b[t];
        s->sdbbs[t] = sdb_b[t]; s->b23s[t] = g_b23[t];
    }
    if (t < 24) { s->sscbs[t] = (t < K_OUT) ? ssc_b[t] : 0.f;
                  s->auxbs[t] = (t < K_OUT) ? aux_b[t] : 0.f; }

    float* outsem = out + (size_t)K_OUT * NVOX;

    const u32 sAh = smem_u32(s->Ah), sAl = smem_u32(s->Al);
    const u32 sB1h = smem_u32(s->B1h), sB1l = smem_u32(s->B1l);
    const u32 sB3h = smem_u32(s->B3h), sB3l = smem_u32(s->B3l);
    const u32 sB4h = smem_u32(s->B4h), sB4l = smem_u32(s->B4l);
    const u32 sB2h = smem_u32(s->B2h), sB2l = smem_u32(s->B2l);
    const u32 sB5h = smem_u32(s->B5h), sB5l = smem_u32(s->B5l);

    const int vt = warp >> 1, nh = warp & 1;
    const int v0 = vt * 16, n0 = nh * 32;
    const int qd = lane >> 3, rw = lane & 7;
    const u32 aoffA = (u32)(((v0 + rw + (qd & 1) * 8) * SA + (qd >> 1) * 8) * 2);
    #define BOFF(nb, S) ((u32)((((nb) + rw + (qd >> 1) * 8) * (S) + (qd & 1) * 8) * 2))
    const u32 b1h0 = sB1h + BOFF(n0, SA),      b1h1 = sB1h + BOFF(n0 + 16, SA);
    const u32 b1l0 = sB1l + BOFF(n0, SA),      b1l1 = sB1l + BOFF(n0 + 16, SA);
    const u32 b3h0 = sB3h + BOFF(n0, SA),      b3h1 = sB3h + BOFF(n0 + 16, SA);
    const u32 b3l0 = sB3l + BOFF(n0, SA),      b3l1 = sB3l + BOFF(n0 + 16, SA);
    const u32 ox2  = (u32)(((16 + rw) * SA + (qd & 1) * 8) * 2);
    const u32 b4h  = nh ? (sB4h + ox2) : (sB4h + BOFF(0, SA));
    const u32 b4l  = nh ? (sB4l + ox2) : (sB4l + BOFF(0, SA));
    const u32 aoffH = (u32)(((v0 + rw + (qd & 1) * 8) * SH + (qd >> 1) * 8) * 2);
    const u32 b2h0 = sB2h + BOFF(n0, SH),      b2h1 = sB2h + BOFF(n0 + 16, SH);
    const u32 b2l0 = sB2l + BOFF(n0, SH),      b2l1 = sB2l + BOFF(n0 + 16, SH);
    const u32 ox2H = (u32)(((16 + rw) * SH + (qd & 1) * 8) * 2);
    const u32 b5h  = nh ? (sB5h + ox2H) : (sB5h + BOFF(0, SH));
    const u32 b5l  = nh ? (sB5l + ox2H) : (sB5l + BOFF(0, SH));

    const int rlo = v0 + (lane >> 2), rhi = rlo + 8;
    const int q4 = lane & 3;
    const int lv = warp * 8 + (lane & 7);
    const int lcq = (lane >> 3) * 2;

    for (int tile = blockIdx.x; tile < NTILES; tile += gridDim.x) {
        __syncthreads();                    // prior tile fully consumed
        const bool masked = tile < NMT;
        const int* idxs = masked ? (mi + tile * TILE) : (ui + (tile - NMT) * TILE);

        // ---- gather + split feats -> Ah/Al [row][c] stride SA ----
        {
            const int gv = __ldg(&idxs[lv]);
            #pragma unroll 4
            for (int i = 0; i < 16; ++i) {
                int c = i * 8 + lcq;
                float f0 = x3d[(size_t)c * NVOX + gv];
                float f1 = x3d[(size_t)(c + 1) * NVOX + gv];
                u32 hi, lo; split2(f0, f1, hi, lo);
                *(u32*)((char*)s->Ah + (lv * SA + c) * 2) = hi;
                *(u32*)((char*)s->Al + (lv * SA + c) * 2) = lo;
            }
        }
        if (t < TILE) s->vidx[t] = idxs[t];
        __syncthreads();

        if (masked) {
            // ========== D1 = feats @ w1 (K=128) ==========
            float d1[4][4] = {};
            {
                const u32 aAh = sAh + aoffA, aAl = sAl + aoffA;
                #pragma unroll
                for (int kt = 0; kt < 8; ++kt) {
                    const u32 ka = kt * 32;
                    u32 ah[4], al[4], bh[4], bl[4];
                    ldsm4(ah, aAh + ka); ldsm4(al, aAl + ka);
                    ldsm4(bh, b1h0 + ka); ldsm4(bl, b1l0 + ka);
                    mmab(d1[0], ah, bh[0], bh[1]); mmab(d1[1], ah, bh[2], bh[3]);
                    mmab(d1[0], ah, bl[0], bl[1]); mmab(d1[1], ah, bl[2], bl[3]);
                    mmab(d1[0], al, bh[0], bh[1]); mmab(d1[1], al, bh[2], bh[3]);
                    ldsm4(bh, b1h1 + ka); ldsm4(bl, b1l1 + ka);
                    mmab(d1[2], ah, bh[0], bh[1]); mmab(d1[3], ah, bh[2], bh[3]);
                    mmab(d1[2], ah, bl[0], bl[1]); mmab(d1[3], ah, bl[2], bl[3]);
                    mmab(d1[2], al, bh[0], bh[1]); mmab(d1[3], al, bh[2], bh[3]);
                }
            }
            // ---- h = D1 + b1 ; LN partials ----
            {
                float slo = 0.f, qlo = 0.f, shi = 0.f, qhi = 0.f;
                #pragma unroll
                for (int nt = 0; nt < 4; ++nt) {
                    int j = n0 + nt * 8 + q4 * 2;
                    float bb0 = s->b1s[j], bb1 = s->b1s[j + 1];
                    d1[nt][0] += bb0; d1[nt][1] += bb1; d1[nt][2] += bb0; d1[nt][3] += bb1;
                    slo += d1[nt][0] + d1[nt][1];
                    qlo += d1[nt][0] * d1[nt][0] + d1[nt][1] * d1[nt][1];
                    shi += d1[nt][2] + d1[nt][3];
                    qhi += d1[nt][2] * d1[nt][2] + d1[nt][3] * d1[nt][3];
                }
                #pragma unroll
                for (int o = 1; o < 4; o <<= 1) {
                    slo += __shfl_xor_sync(0xFFFFFFFFu, slo, o);
                    qlo += __shfl_xor_sync(0xFFFFFFFFu, qlo, o);
                    shi += __shfl_xor_sync(0xFFFFFFFFu, shi, o);
                    qhi += __shfl_xor_sync(0xFFFFFFFFu, qhi, o);
                }
                if (q4 == 0) {
                    s->red1[nh * 128 + rlo] = slo; s->red2[nh * 128 + rlo] = qlo;
                    s->red1[nh * 128 + rhi] = shi; s->red2[nh * 128 + rhi] = qhi;
                }
            }
            __syncthreads();
            if (t < TILE) {
                float su = s->red1[t] + s->red1[128 + t];
                float sq = s->red2[t] + s->red2[128 + t];
                float mu = su * (1.f / 64.f);
                float var = sq * (1.f / 64.f) - mu * mu;
                s->mus[t] = mu; s->rss[t] = rsqrtf(var + 1e-5f);
            }
            __syncthreads();
            // ---- normalize + leaky -> H bf16 hi/lo (stride SH) ----
            {
                float mu0 = s->mus[rlo], rs0 = s->rss[rlo];
                float mu1 = s->mus[rhi], rs1 = s->rss[rhi];
                #pragma unroll
                for (int nt = 0; nt < 4; ++nt) {
                    int j = n0 + nt * 8 + q4 * 2;
                    float g0 = s->lngs[j], g1 = s->lngs[j + 1];
                    float c0 = s->lnbs[j], c1 = s->lnbs[j + 1];
                    float x0 = leaky((d1[nt][0] - mu0) * rs0 * g0 + c0);
                    float x1 = leaky((d1[nt][1] - mu0) * rs0 * g1 + c1);
                    float x2 = leaky((d1[nt][2] - mu1) * rs1 * g0 + c0);
                    float x3 = leaky((d1[nt][3] - mu1) * rs1 * g1 + c1);
                    u32 hi, lo;
                    split2(x0, x1, hi, lo);
                    *(u32*)((char*)s->Ah + (rlo * SH + j) * 2) = hi;
                    *(u32*)((char*)s->Al + (rlo * SH + j) * 2) = lo;
                    split2(x2, x3, hi, lo);
                    *(u32*)((char*)s->Ah + (rhi * SH + j) * 2) = hi;
                    *(u32*)((char*)s->Al + (rhi * SH + j) * 2) = lo;
                }
            }
            __syncthreads();
            // ========== D2 = H @ W23 (K=64) ==========
            float d2[4][4] = {};
            {
                const u32 aHh = sAh + aoffH, aHl = sAl + aoffH;
                #pragma unroll
                for (int kt = 0; kt < 4; ++kt) {
                    const u32 ka = kt * 32;
                    u32 ah[4], al[4], bh[4], bl[4];
                    ldsm4(ah, aHh + ka); ldsm4(al, aHl + ka);
                    ldsm4(bh, b2h0 + ka); ldsm4(bl, b2l0 + ka);
                    mmab(d2[0], ah, bh[0], bh[1]); mmab(d2[1], ah, bh[2], bh[3]);
                    mmab(d2[0], ah, bl[0], bl[1]); mmab(d2[1], ah, bl[2], bl[3]);
                    mmab(d2[0], al, bh[0], bh[1]); mmab(d2[1], al, bh[2], bh[3]);
                    ldsm4(bh, b2h1 + ka); ldsm4(bl, b2l1 + ka);
                    mmab(d2[2], ah, bh[0], bh[1]); mmab(d2[3], ah, bh[2], bh[3]);
                    mmab(d2[2], ah, bl[0], bl[1]); mmab(d2[3], ah, bl[2], bl[3]);
                    mmab(d2[2], al, bh[0], bh[1]); mmab(d2[3], al, bh[2], bh[3]);
                }
            }
            __syncthreads();                // all H reads done
            // ---- d = leaky(D2 + b23) -> bf16 hi/lo in place ----
            {
                #pragma unroll
                for (int nt = 0; nt < 4; ++nt) {
                    int j = n0 + nt * 8 + q4 * 2;
                    float bm0 = s->b23s[j], bm1 = s->b23s[j + 1];
                    float x0 = leaky(d2[nt][0] + bm0);
                    float x1 = leaky(d2[nt][1] + bm1);
                    float x2 = leaky(d2[nt][2] + bm0);
                    float x3 = leaky(d2[nt][3] + bm1);
                    u32 hi, lo;
                    split2(x0, x1, hi, lo);
                    *(u32*)((char*)s->Ah + (rlo * SH + j) * 2) = hi;
                    *(u32*)((char*)s->Al + (rlo * SH + j) * 2) = lo;
                    split2(x2, x3, hi, lo);
                    *(u32*)((char*)s->Ah + (rhi * SH + j) * 2) = hi;
                    *(u32*)((char*)s->Al + (rhi * SH + j) * 2) = lo;
                }
            }
        } else {
            // ========== D3 = feats @ sdb, D4 = feats @ aux (K=128) ==========
            float d3[4][4] = {}, d4[2][4] = {};
            {
                const u32 aAh = sAh + aoffA, aAl = sAl + aoffA;
                #pragma unroll
                for (int kt = 0; kt < 8; ++kt) {
                    const u32 ka = kt * 32;
                    u32 ah[4], al[4], bh[4], bl[4];
                    ldsm4(ah, aAh + ka); ldsm4(al, aAl + ka);
                    ldsm4(bh, b3h0 + ka); ldsm4(bl, b3l0 + ka);
                    mmab(d3[0], ah, bh[0], bh[1]); mmab(d3[1], ah, bh[2], bh[3]);
                    mmab(d3[0], ah, bl[0], bl[1]); mmab(d3[1], ah, bl[2], bl[3]);
                    mmab(d3[0], al, bh[0], bh[1]); mmab(d3[1], al, bh[2], bh[3]);
                    ldsm4(bh, b3h1 + ka); ldsm4(bl, b3l1 + ka);
                    mmab(d3[2], ah, bh[0], bh[1]); mmab(d3[3], ah, bh[2], bh[3]);
                    mmab(d3[2], ah, bl[0], bl[1]); mmab(d3[3], ah, bl[2], bl[3]);
                    mmab(d3[2], al, bh[0], bh[1]); mmab(d3[3], al, bh[2], bh[3]);
                    if (nh == 0) {
                        ldsm4(bh, b4h + ka); ldsm4(bl, b4l + ka);
                        mmab(d4[0], ah, bh[0], bh[1]); mmab(d4[1], ah, bh[2], bh[3]);
                        mmab(d4[0], ah, bl[0], bl[1]); mmab(d4[1], ah, bl[2], bl[3]);
                        mmab(d4[0], al, bh[0], bh[1]); mmab(d4[1], al, bh[2], bh[3]);
                    } else {
                        ldsm2(bh, b4h + ka); ldsm2(bl, b4l + ka);
                        mmab(d4[0], ah, bh[0], bh[1]);
                        mmab(d4[0], ah, bl[0], bl[1]);
                        mmab(d4[0], al, bh[0], bh[1]);
                    }
                }
            }
            // ---- AUX writeback (rank = utile*128 + row, coalesced) ----
            {
                const int rbase = (tile - NMT) * TILE;
                int r0v = rbase + rlo, r1v = rbase + rhi;
                if (nh == 0) {
                    #pragma unroll
                    for (int nt = 0; nt < 2; ++nt) {
                        int k = nt * 8 + q4 * 2;
                        *(float2*)&outsem[(size_t)r0v * K_OUT + k] =
                            make_float2(d4[nt][0] + s->auxbs[k], d4[nt][1] + s->auxbs[k + 1]);
                        *(float2*)&outsem[(size_t)r1v * K_OUT + k] =
                            make_float2(d4[nt][2] + s->auxbs[k], d4[nt][3] + s->auxbs[k + 1]);
                    }
                } else {
                    int k = 16 + q4 * 2;
                    if (k < K_OUT) {
                        *(float2*)&outsem[(size_t)r0v * K_OUT + k] =
                            make_float2(d4[0][0] + s->auxbs[k], d4[0][1] + s->auxbs[k + 1]);
                        *(float2*)&outsem[(size_t)r1v * K_OUT + k] =
                            make_float2(d4[0][2] + s->auxbs[k], d4[0][3] + s->auxbs[k + 1]);
                    }
                }
            }
            __syncthreads();                // all feats(SA) reads done before SH overwrite
            // ---- d = leaky(D3 + sdb_b) -> bf16 hi/lo in place ----
            {
                #pragma unroll
                for (int nt = 0; nt < 4; ++nt) {
                    int j = n0 + nt * 8 + q4 * 2;
                    float bu0 = s->sdbbs[j], bu1 = s->sdbbs[j + 1];
                    float x0 = leaky(d3[nt][0] + bu0);
                    float x1 = leaky(d3[nt][1] + bu1);
                    float x2 = leaky(d3[nt][2] + bu0);
                    float x3 = leaky(d3[nt][3] + bu1);
                    u32 hi, lo;
                    split2(x0, x1, hi, lo);
                    *(u32*)((char*)s->Ah + (rlo * SH + j) * 2) = hi;
                    *(u32*)((char*)s->Al + (rlo * SH + j) * 2) = lo;
                    split2(x2, x3, hi, lo);
                    *(u32*)((char*)s->Ah + (rhi * SH + j) * 2) = hi;
                    *(u32*)((char*)s->Al + (rhi * SH + j) * 2) = lo;
                }
            }
        }
        __syncthreads();                    // all d written

        // ================= D5 = d @ ssc_w (K=64) =================
        float d5[2][4] = {};
        {
            const u32 aHh = sAh + aoffH, aHl = sAl + aoffH;
            #pragma unroll
            for (int kt = 0; kt < 4; ++kt) {
                const u32 ka = kt * 32;
                u32 ah[4], al[4], bh[4], bl[4];
                ldsm4(ah, aHh + ka); ldsm4(al, aHl + ka);
                if (nh == 0) {
                    ldsm4(bh, b5h + ka); ldsm4(bl, b5l + ka);
                    mmab(d5[0], ah, bh[0], bh[1]); mmab(d5[1], ah, bh[2], bh[3]);
                    mmab(d5[0], ah, bl[0], bl[1]); mmab(d5[1], ah, bl[2], bl[3]);
                    mmab(d5[0], al, bh[0], bh[1]); mmab(d5[1], al, bh[2], bh[3]);
                } else {
                    ldsm2(bh, b5h + ka); ldsm2(bl, b5l + ka);
                    mmab(d5[0], ah, bh[0], bh[1]);
                    mmab(d5[0], ah, bl[0], bl[1]);
                    mmab(d5[0], al, bh[0], bh[1]);
                }
            }
        }
        // ---- SSC writeback: scatter via vidx ----
        {
            const int vlo = s->vidx[rlo], vhi = s->vidx[rhi];
            if (nh == 0) {
                #pragma unroll
                for (int nt = 0; nt < 2; ++nt) {
                    int k = nt * 8 + q4 * 2;
                    out[(size_t)k       * NVOX + vlo] = d5[nt][0] + s->sscbs[k];
                    out[(size_t)(k + 1) * NVOX + vlo] = d5[nt][1] + s->sscbs[k + 1];
                    out[(size_t)k       * NVOX + vhi] = d5[nt][2] + s->sscbs[k];
                    out[(size_t)(k + 1) * NVOX + vhi] = d5[nt][3] + s->sscbs[k + 1];
                }
            } else {
                int k = 16 + q4 * 2;
                if (k < K_OUT) {
                    out[(size_t)k       * NVOX + vlo] = d5[0][0] + s->sscbs[k];
                    out[(size_t)(k + 1) * NVOX + vlo] = d5[0][1] + s->sscbs[k + 1];
                    out[(size_t)k       * NVOX + vhi] = d5[0][2] + s->sscbs[k];
                    out[(size_t)(k + 1) * NVOX + vhi] = d5[0][3] + s->sscbs[k + 1];
                }
            }
        }
    }
}

extern "C" void kernel_launch(void* const* d_in, const int* in_sizes, int n_in,
                              void* d_out, int out_size)
{
    const float* x3d   = (const float*)d_in[0];
    const float* w1    = (const float*)d_in[1];
    const float* b1    = (const float*)d_in[2];
    const float* ln_g  = (const float*)d_in[3];
    const float* ln_b  = (const float*)d_in[4];
    const float* w2    = (const float*)d_in[5];
    const float* b2    = (const float*)d_in[6];
    const float* sdb_w = (const float*)d_in[7];
    const float* sdb_b = (const float*)d_in[8];
    const float* ssc_w = (const float*)d_in[9];
    const float* ssc_b = (const float*)d_in[10];
    const float* aux_w = (const float*)d_in[11];
    const float* aux_b = (const float*)d_in[12];
    const int* ui      = (const int*)d_in[13];
    const int* mi      = (const int*)d_in[14];
    float* out         = (float*)d_out;

    int nsm = 0;
    cudaDeviceGetAttribute(&nsm, cudaDevAttrMultiProcessorCount, 0);
    if (nsm <= 0) nsm = 148;

    cudaFuncSetAttribute(fused_kernel,
                         cudaFuncAttributeMaxDynamicSharedMemorySize,
                         (int)sizeof(Smem));

    w23_kernel<<<16, 256>>>(w2, sdb_w, b2, sdb_b);
    fused_kernel<<<nsm, THREADS, sizeof(Smem)>>>(x3d, w1, b1, ln_g, ln_b,
                                                 sdb_w, sdb_b, ssc_w, ssc_b,
                                                 aux_w, aux_b, ui, mi, out);
}

// round 13
// speedup vs baseline: 2.4760x; 1.2384x over previous
#include <cuda_runtime.h>
#include <cuda_bf16.h>

#define NVOX   262144
#define NU     65536
#define NM     (NVOX - NU)
#define C_IN   128
#define C_HID  64
#define K_OUT  20
#define TILE   64
#define MT     (NM / TILE)        // 3072 masked tiles
#define UT     (NU / TILE)        // 1024 unmasked tiles
#define SA     136                // feats/B1/B3/B4 row stride (bf16 elems)
#define SH     72                 // H,d / B2,B5 row stride
#define THREADS 256

typedef unsigned int u32;
typedef unsigned short u16;

__device__ __forceinline__ float leaky(float x) {
    return fmaxf(x, 0.f) + 0.01f * fminf(x, 0.f);
}
__device__ __forceinline__ u16 f2bf(float x) {
    return __bfloat16_as_ushort(__float2bfloat16(x));
}
__device__ __forceinline__ float bf2f(u16 b) {
    return __bfloat162float(__ushort_as_bfloat16(b));
}
__device__ __forceinline__ void split2(float x0, float x1, u32& hi, u32& lo) {
    u16 h0 = f2bf(x0), h1 = f2bf(x1);
    u16 l0 = f2bf(x0 - bf2f(h0)), l1 = f2bf(x1 - bf2f(h1));
    hi = (u32)h0 | ((u32)h1 << 16);
    lo = (u32)l0 | ((u32)l1 << 16);
}
__device__ __forceinline__ u32 smem_u32(const void* p) {
    u32 a; asm("{ .reg .u64 t; cvta.to.shared.u64 t, %1; cvt.u32.u64 %0, t; }" : "=r"(a) : "l"(p));
    return a;
}
__device__ __forceinline__ void ldsm4(u32* r, u32 addr) {
    asm volatile("ldmatrix.sync.aligned.m8n8.x4.shared.b16 {%0,%1,%2,%3}, [%4];"
                 : "=r"(r[0]), "=r"(r[1]), "=r"(r[2]), "=r"(r[3]) : "r"(addr));
}
__device__ __forceinline__ void ldsm2(u32* r, u32 addr) {
    asm volatile("ldmatrix.sync.aligned.m8n8.x2.shared.b16 {%0,%1}, [%2];"
                 : "=r"(r[0]), "=r"(r[1]) : "r"(addr));
}
__device__ __forceinline__ void mmab(float* c, const u32* a, u32 b0, u32 b1) {
    asm volatile("mma.sync.aligned.m16n8k16.row.col.f32.bf16.bf16.f32 "
                 "{%0,%1,%2,%3}, {%4,%5,%6,%7}, {%8,%9}, {%0,%1,%2,%3};"
                 : "+f"(c[0]), "+f"(c[1]), "+f"(c[2]), "+f"(c[3])
                 : "r"(a[0]), "r"(a[1]), "r"(a[2]), "r"(a[3]), "r"(b0), "r"(b1));
}

__device__ float g_W23[C_HID * C_HID];
__device__ float g_b23[C_HID];

__global__ void w23_kernel(const float* __restrict__ w2, const float* __restrict__ sdb_w,
                           const float* __restrict__ b2, const float* __restrict__ sdb_b) {
    int idx = blockIdx.x * blockDim.x + threadIdx.x;
    if (idx < C_HID * C_HID) {
        int j = idx >> 6, j2 = idx & 63;
        float acc = 0.f;
        #pragma unroll 8
        for (int c = 0; c < C_IN; ++c) acc += w2[j * C_IN + c] * sdb_w[c * C_HID + j2];
        g_W23[idx] = acc;
    }
    if (idx < C_HID) {
        float acc = sdb_b[idx];
        #pragma unroll 8
        for (int c = 0; c < C_IN; ++c) acc += b2[c] * sdb_w[c * C_HID + idx];
        g_b23[idx] = acc;
    }
}

struct SmemM {                              // masked role
    u16 Ah[TILE * SA], Al[TILE * SA];       // feats (SA); later H / d (SH)
    u16 B1h[64 * SA], B1l[64 * SA];         // w1  [j][c]
    u16 B2h[64 * SH], B2l[64 * SH];         // W23 [j2][j]
    u16 B5h[24 * SH], B5l[24 * SH];         // ssc [k][j2]
    float b1s[64], lngs[64], lnbs[64], b23s[64];
    float sscbs[24];
    float mus[TILE], rss[TILE];
    float red1[2 * TILE], red2[2 * TILE];
    int   vidx[TILE];
};
struct SmemU {                              // unmasked role
    u16 Ah[TILE * SA], Al[TILE * SA];
    u16 B3h[64 * SA], B3l[64 * SA];         // sdb [j][c]
    u16 B4h[24 * SA], B4l[24 * SA];         // aux [k][c]
    u16 B5h[24 * SH], B5l[24 * SH];         // ssc [k][j2]
    float sdbbs[64];
    float sscbs[24], auxbs[24];
    int   vidx[TILE];
};
#define SMEM_MAX ((int)(sizeof(SmemM) > sizeof(SmemU) ? sizeof(SmemM) : sizeof(SmemU)))

__global__ void __launch_bounds__(THREADS, 2)
fused_kernel(const float* __restrict__ x3d,
             const float* __restrict__ w1,    const float* __restrict__ b1,
             const float* __restrict__ ln_g,  const float* __restrict__ ln_b,
             const float* __restrict__ sdb_w, const float* __restrict__ sdb_b,
             const float* __restrict__ ssc_w, const float* __restrict__ ssc_b,
             const float* __restrict__ aux_w, const float* __restrict__ aux_b,
             const int* __restrict__ ui,      const int* __restrict__ mi,
             float* __restrict__ out, int mblocks)
{
    extern __shared__ char smem_raw[];
    const int t = threadIdx.x;
    const int warp = t >> 5, lane = t & 31;
    const int nblocks = gridDim.x;

    // fragment geometry (role-independent)
    const int vt = warp >> 1, nh = warp & 1;
    const int v0 = vt * 16, n0 = nh * 32;
    const int qd = lane >> 3, rw = lane & 7;
    const u32 aoffA = (u32)(((v0 + rw + (qd & 1) * 8) * SA + (qd >> 1) * 8) * 2);
    const u32 aoffH = (u32)(((v0 + rw + (qd & 1) * 8) * SH + (qd >> 1) * 8) * 2);
    #define BOFF(nb, S) ((u32)((((nb) + rw + (qd >> 1) * 8) * (S) + (qd & 1) * 8) * 2))
    const int rlo = v0 + (lane >> 2), rhi = rlo + 8;
    const int q4 = lane & 3;
    const int lv = warp * 8 + (lane & 7);       // loader row 0..63
    const int lcq = (lane >> 3) * 2;

    float* outsem = out + (size_t)K_OUT * NVOX;

    if (blockIdx.x < mblocks) {
        // ================= MASKED ROLE =================
        SmemM* s = reinterpret_cast<SmemM*>(smem_raw);
        for (int i = t; i < 64 * 128; i += THREADS) {
            int j = i & 63, c = i >> 6;
            float x = w1[c * C_HID + j];
            u16 h = f2bf(x); s->B1h[j * SA + c] = h; s->B1l[j * SA + c] = f2bf(x - bf2f(h));
        }
        for (int i = t; i < 64 * 64; i += THREADS) {
            int j2 = i & 63, j = i >> 6;
            float x = g_W23[j * C_HID + j2];
            u16 h = f2bf(x); s->B2h[j2 * SH + j] = h; s->B2l[j2 * SH + j] = f2bf(x - bf2f(h));
        }
        for (int i = t; i < 24 * SH; i += THREADS) { s->B5h[i] = 0; s->B5l[i] = 0; }
        __syncthreads();
        for (int i = t; i < 64 * K_OUT; i += THREADS) {
            int k = i % K_OUT, j = i / K_OUT;
            float x = ssc_w[j * K_OUT + k];
            u16 h = f2bf(x); s->B5h[k * SH + j] = h; s->B5l[k * SH + j] = f2bf(x - bf2f(h));
        }
        if (t < C_HID) {
            s->b1s[t] = b1[t]; s->lngs[t] = ln_g[t]; s->lnbs[t] = ln_b[t]; s->b23s[t] = g_b23[t];
        }
        if (t < 24) s->sscbs[t] = (t < K_OUT) ? ssc_b[t] : 0.f;

        const u32 sAh = smem_u32(s->Ah), sAl = smem_u32(s->Al);
        const u32 sB1h = smem_u32(s->B1h), sB1l = smem_u32(s->B1l);
        const u32 sB2h = smem_u32(s->B2h), sB2l = smem_u32(s->B2l);
        const u32 sB5h = smem_u32(s->B5h), sB5l = smem_u32(s->B5l);
        const u32 b1h0 = sB1h + BOFF(n0, SA), b1h1 = sB1h + BOFF(n0 + 16, SA);
        const u32 b1l0 = sB1l + BOFF(n0, SA), b1l1 = sB1l + BOFF(n0 + 16, SA);
        const u32 b2h0 = sB2h + BOFF(n0, SH), b2h1 = sB2h + BOFF(n0 + 16, SH);
        const u32 b2l0 = sB2l + BOFF(n0, SH), b2l1 = sB2l + BOFF(n0 + 16, SH);
        const u32 ox2H = (u32)(((16 + rw) * SH + (qd & 1) * 8) * 2);
        const u32 b5h = nh ? (sB5h + ox2H) : (sB5h + BOFF(0, SH));
        const u32 b5l = nh ? (sB5l + ox2H) : (sB5l + BOFF(0, SH));

        for (int tile = blockIdx.x; tile < MT; tile += mblocks) {
            __syncthreads();
            const int* idxs = mi + tile * TILE;
            {
                const int gv = __ldg(&idxs[lv]);
                #pragma unroll 4
                for (int i = 0; i < 16; ++i) {
                    int c = i * 8 + lcq;
                    float f0 = x3d[(size_t)c * NVOX + gv];
                    float f1 = x3d[(size_t)(c + 1) * NVOX + gv];
                    u32 hi, lo; split2(f0, f1, hi, lo);
                    *(u32*)((char*)s->Ah + (lv * SA + c) * 2) = hi;
                    *(u32*)((char*)s->Al + (lv * SA + c) * 2) = lo;
                }
            }
            if (t < TILE) s->vidx[t] = idxs[t];
            __syncthreads();

            // D1 = feats @ w1 (K=128)
            float d1[4][4] = {};
            {
                const u32 aAh = sAh + aoffA, aAl = sAl + aoffA;
                #pragma unroll
                for (int kt = 0; kt < 8; ++kt) {
                    const u32 ka = kt * 32;
                    u32 ah[4], al[4], bh[4], bl[4];
                    ldsm4(ah, aAh + ka); ldsm4(al, aAl + ka);
                    ldsm4(bh, b1h0 + ka); ldsm4(bl, b1l0 + ka);
                    mmab(d1[0], ah, bh[0], bh[1]); mmab(d1[1], ah, bh[2], bh[3]);
                    mmab(d1[0], ah, bl[0], bl[1]); mmab(d1[1], ah, bl[2], bl[3]);
                    mmab(d1[0], al, bh[0], bh[1]); mmab(d1[1], al, bh[2], bh[3]);
                    ldsm4(bh, b1h1 + ka); ldsm4(bl, b1l1 + ka);
                    mmab(d1[2], ah, bh[0], bh[1]); mmab(d1[3], ah, bh[2], bh[3]);
                    mmab(d1[2], ah, bl[0], bl[1]); mmab(d1[3], ah, bl[2], bl[3]);
                    mmab(d1[2], al, bh[0], bh[1]); mmab(d1[3], al, bh[2], bh[3]);
                }
            }
            // h = D1 + b1; LN partials
            {
                float slo = 0.f, qlo = 0.f, shi = 0.f, qhi = 0.f;
                #pragma unroll
                for (int nt = 0; nt < 4; ++nt) {
                    int j = n0 + nt * 8 + q4 * 2;
                    float bb0 = s->b1s[j], bb1 = s->b1s[j + 1];
                    d1[nt][0] += bb0; d1[nt][1] += bb1; d1[nt][2] += bb0; d1[nt][3] += bb1;
                    slo += d1[nt][0] + d1[nt][1];
                    qlo += d1[nt][0] * d1[nt][0] + d1[nt][1] * d1[nt][1];
                    shi += d1[nt][2] + d1[nt][3];
                    qhi += d1[nt][2] * d1[nt][2] + d1[nt][3] * d1[nt][3];
                }
                #pragma unroll
                for (int o = 1; o < 4; o <<= 1) {
                    slo += __shfl_xor_sync(0xFFFFFFFFu, slo, o);
                    qlo += __shfl_xor_sync(0xFFFFFFFFu, qlo, o);
                    shi += __shfl_xor_sync(0xFFFFFFFFu, shi, o);
                    qhi += __shfl_xor_sync(0xFFFFFFFFu, qhi, o);
                }
                if (q4 == 0) {
                    s->red1[nh * TILE + rlo] = slo; s->red2[nh * TILE + rlo] = qlo;
                    s->red1[nh * TILE + rhi] = shi; s->red2[nh * TILE + rhi] = qhi;
                }
            }
            __syncthreads();
            if (t < TILE) {
                float su = s->red1[t] + s->red1[TILE + t];
                float sq = s->red2[t] + s->red2[TILE + t];
                float mu = su * (1.f / 64.f);
                float var = sq * (1.f / 64.f) - mu * mu;
                s->mus[t] = mu; s->rss[t] = rsqrtf(var + 1e-5f);
            }
            __syncthreads();
            // normalize + leaky -> H (SH)
            {
                float mu0 = s->mus[rlo], rs0 = s->rss[rlo];
                float mu1 = s->mus[rhi], rs1 = s->rss[rhi];
                #pragma unroll
                for (int nt = 0; nt < 4; ++nt) {
                    int j = n0 + nt * 8 + q4 * 2;
                    float g0 = s->lngs[j], g1 = s->lngs[j + 1];
                    float c0 = s->lnbs[j], c1 = s->lnbs[j + 1];
                    float x0 = leaky((d1[nt][0] - mu0) * rs0 * g0 + c0);
                    float x1 = leaky((d1[nt][1] - mu0) * rs0 * g1 + c1);
                    float x2 = leaky((d1[nt][2] - mu1) * rs1 * g0 + c0);
                    float x3 = leaky((d1[nt][3] - mu1) * rs1 * g1 + c1);
                    u32 hi, lo;
                    split2(x0, x1, hi, lo);
                    *(u32*)((char*)s->Ah + (rlo * SH + j) * 2) = hi;
                    *(u32*)((char*)s->Al + (rlo * SH + j) * 2) = lo;
                    split2(x2, x3, hi, lo);
                    *(u32*)((char*)s->Ah + (rhi * SH + j) * 2) = hi;
                    *(u32*)((char*)s->Al + (rhi * SH + j) * 2) = lo;
                }
            }
            __syncthreads();
            // D2 = H @ W23 (K=64)
            float d2[4][4] = {};
            {
                const u32 aHh = sAh + aoffH, aHl = sAl + aoffH;
                #pragma unroll
                for (int kt = 0; kt < 4; ++kt) {
                    const u32 ka = kt * 32;
                    u32 ah[4], al[4], bh[4], bl[4];
                    ldsm4(ah, aHh + ka); ldsm4(al, aHl + ka);
                    ldsm4(bh, b2h0 + ka); ldsm4(bl, b2l0 + ka);
                    mmab(d2[0], ah, bh[0], bh[1]); mmab(d2[1], ah, bh[2], bh[3]);
                    mmab(d2[0], ah, bl[0], bl[1]); mmab(d2[1], ah, bl[2], bl[3]);
                    mmab(d2[0], al, bh[0], bh[1]); mmab(d2[1], al, bh[2], bh[3]);
                    ldsm4(bh, b2h1 + ka); ldsm4(bl, b2l1 + ka);
                    mmab(d2[2], ah, bh[0], bh[1]); mmab(d2[3], ah, bh[2], bh[3]);
                    mmab(d2[2], ah, bl[0], bl[1]); mmab(d2[3], ah, bl[2], bl[3]);
                    mmab(d2[2], al, bh[0], bh[1]); mmab(d2[3], al, bh[2], bh[3]);
                }
            }
            __syncthreads();
            // d = leaky(D2 + b23) -> bf16 in place
            {
                #pragma unroll
                for (int nt = 0; nt < 4; ++nt) {
                    int j = n0 + nt * 8 + q4 * 2;
                    float bm0 = s->b23s[j], bm1 = s->b23s[j + 1];
                    float x0 = leaky(d2[nt][0] + bm0);
                    float x1 = leaky(d2[nt][1] + bm1);
                    float x2 = leaky(d2[nt][2] + bm0);
                    float x3 = leaky(d2[nt][3] + bm1);
                    u32 hi, lo;
                    split2(x0, x1, hi, lo);
                    *(u32*)((char*)s->Ah + (rlo * SH + j) * 2) = hi;
                    *(u32*)((char*)s->Al + (rlo * SH + j) * 2) = lo;
                    split2(x2, x3, hi, lo);
                    *(u32*)((char*)s->Ah + (rhi * SH + j) * 2) = hi;
                    *(u32*)((char*)s->Al + (rhi * SH + j) * 2) = lo;
                }
            }
            __syncthreads();
            // D5 = d @ ssc (K=64)
            float d5[2][4] = {};
            {
                const u32 aHh = sAh + aoffH, aHl = sAl + aoffH;
                #pragma unroll
                for (int kt = 0; kt < 4; ++kt) {
                    const u32 ka = kt * 32;
                    u32 ah[4], al[4], bh[4], bl[4];
                    ldsm4(ah, aHh + ka); ldsm4(al, aHl + ka);
                    if (nh == 0) {
                        ldsm4(bh, b5h + ka); ldsm4(bl, b5l + ka);
                        mmab(d5[0], ah, bh[0], bh[1]); mmab(d5[1], ah, bh[2], bh[3]);
                        mmab(d5[0], ah, bl[0], bl[1]); mmab(d5[1], ah, bl[2], bl[3]);
                        mmab(d5[0], al, bh[0], bh[1]); mmab(d5[1], al, bh[2], bh[3]);
                    } else {
                        ldsm2(bh, b5h + ka); ldsm2(bl, b5l + ka);
                        mmab(d5[0], ah, bh[0], bh[1]);
                        mmab(d5[0], ah, bl[0], bl[1]);
                        mmab(d5[0], al, bh[0], bh[1]);
                    }
                }
            }
            {
                const int vlo = s->vidx[rlo], vhi = s->vidx[rhi];
                if (nh == 0) {
                    #pragma unroll
                    for (int nt = 0; nt < 2; ++nt) {
                        int k = nt * 8 + q4 * 2;
                        out[(size_t)k       * NVOX + vlo] = d5[nt][0] + s->sscbs[k];
                        out[(size_t)(k + 1) * NVOX + vlo] = d5[nt][1] + s->sscbs[k + 1];
                        out[(size_t)k       * NVOX + vhi] = d5[nt][2] + s->sscbs[k];
                        out[(size_t)(k + 1) * NVOX + vhi] = d5[nt][3] + s->sscbs[k + 1];
                    }
                } else {
                    int k = 16 + q4 * 2;
                    if (k < K_OUT) {
                        out[(size_t)k       * NVOX + vlo] = d5[0][0] + s->sscbs[k];
                        out[(size_t)(k + 1) * NVOX + vlo] = d5[0][1] + s->sscbs[k + 1];
                        out[(size_t)k       * NVOX + vhi] = d5[0][2] + s->sscbs[k];
                        out[(size_t)(k + 1) * NVOX + vhi] = d5[0][3] + s->sscbs[k + 1];
                    }
                }
            }
        }
    } else {
        // ================= UNMASKED ROLE =================
        SmemU* s = reinterpret_cast<SmemU*>(smem_raw);
        const int ublocks = nblocks - mblocks;
        const int ubid = blockIdx.x - mblocks;
        for (int i = t; i < 24 * SA; i += THREADS) { s->B4h[i] = 0; s->B4l[i] = 0; }
        for (int i = t; i < 24 * SH; i += THREADS) { s->B5h[i] = 0; s->B5l[i] = 0; }
        __syncthreads();
        for (int i = t; i < 64 * 128; i += THREADS) {
            int j = i & 63, c = i >> 6;
            float x = sdb_w[c * C_HID + j];
            u16 h = f2bf(x); s->B3h[j * SA + c] = h; s->B3l[j * SA + c] = f2bf(x - bf2f(h));
        }
        for (int i = t; i < K_OUT * 128; i += THREADS) {
            int k = i % K_OUT, c = i / K_OUT;
            float x = aux_w[c * K_OUT + k];
            u16 h = f2bf(x); s->B4h[k * SA + c] = h; s->B4l[k * SA + c] = f2bf(x - bf2f(h));
        }
        for (int i = t; i < 64 * K_OUT; i += THREADS) {
            int k = i % K_OUT, j = i / K_OUT;
            float x = ssc_w[j * K_OUT + k];
            u16 h = f2bf(x); s->B5h[k * SH + j] = h; s->B5l[k * SH + j] = f2bf(x - bf2f(h));
        }
        if (t < C_HID) s->sdbbs[t] = sdb_b[t];
        if (t < 24) { s->sscbs[t] = (t < K_OUT) ? ssc_b[t] : 0.f;
                      s->auxbs[t] = (t < K_OUT) ? aux_b[t] : 0.f; }

        const u32 sAh = smem_u32(s->Ah), sAl = smem_u32(s->Al);
        const u32 sB3h = smem_u32(s->B3h), sB3l = smem_u32(s->B3l);
        const u32 sB4h = smem_u32(s->B4h), sB4l = smem_u32(s->B4l);
        const u32 sB5h = smem_u32(s->B5h), sB5l = smem_u32(s->B5l);
        const u32 b3h0 = sB3h + BOFF(n0, SA), b3h1 = sB3h + BOFF(n0 + 16, SA);
        const u32 b3l0 = sB3l + BOFF(n0, SA), b3l1 = sB3l + BOFF(n0 + 16, SA);
        const u32 ox2 = (u32)(((16 + rw) * SA + (qd & 1) * 8) * 2);
        const u32 b4h = nh ? (sB4h + ox2) : (sB4h + BOFF(0, SA));
        const u32 b4l = nh ? (sB4l + ox2) : (sB4l + BOFF(0, SA));
        const u32 ox2H = (u32)(((16 + rw) * SH + (qd & 1) * 8) * 2);
        const u32 b5h = nh ? (sB5h + ox2H) : (sB5h + BOFF(0, SH));
        const u32 b5l = nh ? (sB5l + ox2H) : (sB5l + BOFF(0, SH));

        for (int tile = ubid; tile < UT; tile += ublocks) {
            __syncthreads();
            const int* idxs = ui + tile * TILE;
            {
                const int gv = __ldg(&idxs[lv]);
                #pragma unroll 4
                for (int i = 0; i < 16; ++i) {
                    int c = i * 8 + lcq;
                    float f0 = x3d[(size_t)c * NVOX + gv];
                    float f1 = x3d[(size_t)(c + 1) * NVOX + gv];
                    u32 hi, lo; split2(f0, f1, hi, lo);
                    *(u32*)((char*)s->Ah + (lv * SA + c) * 2) = hi;
                    *(u32*)((char*)s->Al + (lv * SA + c) * 2) = lo;
                }
            }
            if (t < TILE) s->vidx[t] = idxs[t];
            __syncthreads();

            // D3 = feats @ sdb, D4 = feats @ aux (K=128)
            float d3[4][4] = {}, d4[2][4] = {};
            {
                const u32 aAh = sAh + aoffA, aAl = sAl + aoffA;
                #pragma unroll
                for (int kt = 0; kt < 8; ++kt) {
                    const u32 ka = kt * 32;
                    u32 ah[4], al[4], bh[4], bl[4];
                    ldsm4(ah, aAh + ka); ldsm4(al, aAl + ka);
                    ldsm4(bh, b3h0 + ka); ldsm4(bl, b3l0 + ka);
                    mmab(d3[0], ah, bh[0], bh[1]); mmab(d3[1], ah, bh[2], bh[3]);
                    mmab(d3[0], ah, bl[0], bl[1]); mmab(d3[1], ah, bl[2], bl[3]);
                    mmab(d3[0], al, bh[0], bh[1]); mmab(d3[1], al, bh[2], bh[3]);
                    ldsm4(bh, b3h1 + ka); ldsm4(bl, b3l1 + ka);
                    mmab(d3[2], ah, bh[0], bh[1]); mmab(d3[3], ah, bh[2], bh[3]);
                    mmab(d3[2], ah, bl[0], bl[1]); mmab(d3[3], ah, bl[2], bl[3]);
                    mmab(d3[2], al, bh[0], bh[1]); mmab(d3[3], al, bh[2], bh[3]);
                    if (nh == 0) {
                        ldsm4(bh, b4h + ka); ldsm4(bl, b4l + ka);
                        mmab(d4[0], ah, bh[0], bh[1]); mmab(d4[1], ah, bh[2], bh[3]);
                        mmab(d4[0], ah, bl[0], bl[1]); mmab(d4[1], ah, bl[2], bl[3]);
                        mmab(d4[0], al, bh[0], bh[1]); mmab(d4[1], al, bh[2], bh[3]);
                    } else {
                        ldsm2(bh, b4h + ka); ldsm2(bl, b4l + ka);
                        mmab(d4[0], ah, bh[0], bh[1]);
                        mmab(d4[0], ah, bl[0], bl[1]);
                        mmab(d4[0], al, bh[0], bh[1]);
                    }
                }
            }
            // AUX writeback: rank = tile*64 + row
            {
                const int rbase = tile * TILE;
                int r0v = rbase + rlo, r1v = rbase + rhi;
                if (nh == 0) {
                    #pragma unroll
                    for (int nt = 0; nt < 2; ++nt) {
                        int k = nt * 8 + q4 * 2;
                        *(float2*)&outsem[(size_t)r0v * K_OUT + k] =
                            make_float2(d4[nt][0] + s->auxbs[k], d4[nt][1] + s->auxbs[k + 1]);
                        *(float2*)&outsem[(size_t)r1v * K_OUT + k] =
                            make_float2(d4[nt][2] + s->auxbs[k], d4[nt][3] + s->auxbs[k + 1]);
                    }
                } else {
                    int k = 16 + q4 * 2;
                    if (k < K_OUT) {
                        *(float2*)&outsem[(size_t)r0v * K_OUT + k] =
                            make_float2(d4[0][0] + s->auxbs[k], d4[0][1] + s->auxbs[k + 1]);
                        *(float2*)&outsem[(size_t)r1v * K_OUT + k] =
                            make_float2(d4[0][2] + s->auxbs[k], d4[0][3] + s->auxbs[k + 1]);
                    }
                }
            }
            __syncthreads();                // feats(SA) reads done before SH overwrite
            // d = leaky(D3 + sdb_b) -> bf16 in place
            {
                #pragma unroll
                for (int nt = 0; nt < 4; ++nt) {
                    int j = n0 + nt * 8 + q4 * 2;
                    float bu0 = s->sdbbs[j], bu1 = s->sdbbs[j + 1];
                    float x0 = leaky(d3[nt][0] + bu0);
                    float x1 = leaky(d3[nt][1] + bu1);
                    float x2 = leaky(d3[nt][2] + bu0);
                    float x3 = leaky(d3[nt][3] + bu1);
                    u32 hi, lo;
                    split2(x0, x1, hi, lo);
                    *(u32*)((char*)s->Ah + (rlo * SH + j) * 2) = hi;
                    *(u32*)((char*)s->Al + (rlo * SH + j) * 2) = lo;
                    split2(x2, x3, hi, lo);
                    *(u32*)((char*)s->Ah + (rhi * SH + j) * 2) = hi;
                    *(u32*)((char*)s->Al + (rhi * SH + j) * 2) = lo;
                }
            }
            __syncthreads();
            // D5 = d @ ssc (K=64)
            float d5[2][4] = {};
            {
                const u32 aHh = sAh + aoffH, aHl = sAl + aoffH;
                #pragma unroll
                for (int kt = 0; kt < 4; ++kt) {
                    const u32 ka = kt * 32;
                    u32 ah[4], al[4], bh[4], bl[4];
                    ldsm4(ah, aHh + ka); ldsm4(al, aHl + ka);
                    if (nh == 0) {
                        ldsm4(bh, b5h + ka); ldsm4(bl, b5l + ka);
                        mmab(d5[0], ah, bh[0], bh[1]); mmab(d5[1], ah, bh[2], bh[3]);
                        mmab(d5[0], ah, bl[0], bl[1]); mmab(d5[1], ah, bl[2], bl[3]);
                        mmab(d5[0], al, bh[0], bh[1]); mmab(d5[1], al, bh[2], bh[3]);
                    } else {
                        ldsm2(bh, b5h + ka); ldsm2(bl, b5l + ka);
                        mmab(d5[0], ah, bh[0], bh[1]);
                        mmab(d5[0], ah, bl[0], bl[1]);
                        mmab(d5[0], al, bh[0], bh[1]);
                    }
                }
            }
            {
                const int vlo = s->vidx[rlo], vhi = s->vidx[rhi];
                if (nh == 0) {
                    #pragma unroll
                    for (int nt = 0; nt < 2; ++nt) {
                        int k = nt * 8 + q4 * 2;
                        out[(size_t)k       * NVOX + vlo] = d5[nt][0] + s->sscbs[k];
                        out[(size_t)(k + 1) * NVOX + vlo] = d5[nt][1] + s->sscbs[k + 1];
                        out[(size_t)k       * NVOX + vhi] = d5[nt][2] + s->sscbs[k];
                        out[(size_t)(k + 1) * NVOX + vhi] = d5[nt][3] + s->sscbs[k + 1];
                    }
                } else {
                    int k = 16 + q4 * 2;
                    if (k < K_OUT) {
                        out[(size_t)k       * NVOX + vlo] = d5[0][0] + s->sscbs[k];
                        out[(size_t)(k + 1) * NVOX + vlo] = d5[0][1] + s->sscbs[k + 1];
                        out[(size_t)k       * NVOX + vhi] = d5[0][2] + s->sscbs[k];
                        out[(size_t)(k + 1) * NVOX + vhi] = d5[0][3] + s->sscbs[k + 1];
                    }
                }
            }
        }
    }
}

extern "C" void kernel_launch(void* const* d_in, const int* in_sizes, int n_in,
                              void* d_out, int out_size)
{
    const float* x3d   = (const float*)d_in[0];
    const float* w1    = (const float*)d_in[1];
    const float* b1    = (const float*)d_in[2];
    const float* ln_g  = (const float*)d_in[3];
    const float* ln_b  = (const float*)d_in[4];
    const float* w2    = (const float*)d_in[5];
    const float* b2    = (const float*)d_in[6];
    const float* sdb_w = (const float*)d_in[7];
    const float* sdb_b = (const float*)d_in[8];
    const float* ssc_w = (const float*)d_in[9];
    const float* ssc_b = (const float*)d_in[10];
    const float* aux_w = (const float*)d_in[11];
    const float* aux_b = (const float*)d_in[12];
    const int* ui      = (const int*)d_in[13];
    const int* mi      = (const int*)d_in[14];
    float* out         = (float*)d_out;

    int nsm = 0;
    cudaDeviceGetAttribute(&nsm, cudaDevAttrMultiProcessorCount, 0);
    if (nsm <= 0) nsm = 148;

    int blocks  = 2 * nsm;
    int mblocks = (blocks * 3) / 4;       // 3:1 masked:unmasked tile ratio

    cudaFuncSetAttribute(fused_kernel,
                         cudaFuncAttributeMaxDynamicSharedMemorySize, SMEM_MAX);

    w23_kernel<<<16, 256>>>(w2, sdb_w, b2, sdb_b);
    fused_kernel<<<blocks, THREADS, SMEM_MAX>>>(x3d, w1, b1, ln_g, ln_b,
                                                sdb_w, sdb_b, ssc_w, ssc_b,
                                                aux_w, aux_b, ui, mi, out, mblocks);
}